// round 11
// baseline (speedup 1.0000x reference)
#include <cuda_runtime.h>
#include <cuda_fp16.h>
#include <math.h>

#define NN   2048
#define TT   5
#define DD   64
#define KK   21
#define BB   32
#define ROWS (BB*NN)
#define AGG_BLOCKS (ROWS/64)   // 1024

// ---- scratch (device globals; no runtime allocation) ----
__device__ float  g_cos[NN*NN];      // 16 MB
__device__ float  g_norm[NN];
__device__ float  g_ces[NN];         // emb . a_src[64:]
__device__ float  g_ced[NN];         // emb . a_dst[64:]
__device__ float  g_ws[TT];          // W^T a_src[:64]
__device__ float  g_wd[TT];
__device__ float  g_bs[2];           // Wb.a_src[:64], Wb.a_dst[:64]
__device__ int    g_idx[NN*KK];
__device__ __half g_h[ROWS*DD];      // 8 MB (fp16; only consumer is agg gather)
__device__ float  g_esrc[ROWS];
__device__ float  g_edst[ROWS];
__device__ __half g_obuf[ROWS*DD];   // 8 MB (fp16)
__device__ float  g_part2[AGG_BLOCKS*128];  // per agg block: 64 sums + 64 sumsqs
__device__ float  g_mean[DD];
__device__ float  g_inv[DD];

// monotonic float->uint key (total order matches float >)
__device__ __forceinline__ unsigned fkey(float f) {
    unsigned b = __float_as_uint(f);
    return (b & 0x80000000u) ? ~b : (b | 0x80000000u);
}

// ---------------------------------------------------------------------------
// 1) pre: per-node norms + emb-attention constants; warp 0 of block 0 also
//    computes the 5-dim projected attention weights.
__global__ __launch_bounds__(256) void pre_kernel(
    const float* __restrict__ emb, const float* __restrict__ W,
    const float* __restrict__ Wb,
    const float* __restrict__ a_src, const float* __restrict__ a_dst) {
    int t = threadIdx.x, lane = t & 31, w = t >> 5;
    int n = blockIdx.x * 8 + w;

    float e0 = emb[n * DD + lane], e1 = emb[n * DD + lane + 32];
    float s  = e0 * e0 + e1 * e1;
    float ps = e0 * a_src[DD + lane] + e1 * a_src[DD + lane + 32];
    float pd = e0 * a_dst[DD + lane] + e1 * a_dst[DD + lane + 32];
    #pragma unroll
    for (int off = 16; off; off >>= 1) {
        s  += __shfl_down_sync(0xffffffffu, s, off);
        ps += __shfl_down_sync(0xffffffffu, ps, off);
        pd += __shfl_down_sync(0xffffffffu, pd, off);
    }
    if (lane == 0) {
        g_norm[n] = sqrtf(s);
        g_ces[n] = ps;
        g_ced[n] = pd;
    }

    if (blockIdx.x == 0 && w == 0) {
        float a0 = a_src[lane], a1 = a_src[lane + 32];
        float d0 = a_dst[lane], d1 = a_dst[lane + 32];
        #pragma unroll
        for (int tt = 0; tt < TT; tt++) {
            float w0 = W[lane * TT + tt], w1 = W[(lane + 32) * TT + tt];
            float vs = w0 * a0 + w1 * a1;
            float vd = w0 * d0 + w1 * d1;
            #pragma unroll
            for (int off = 16; off; off >>= 1) {
                vs += __shfl_down_sync(0xffffffffu, vs, off);
                vd += __shfl_down_sync(0xffffffffu, vd, off);
            }
            if (lane == 0) { g_ws[tt] = vs; g_wd[tt] = vd; }
        }
        float b0 = Wb[lane], b1 = Wb[lane + 32];
        float vbs = b0 * a0 + b1 * a1;
        float vbd = b0 * d0 + b1 * d1;
        #pragma unroll
        for (int off = 16; off; off >>= 1) {
            vbs += __shfl_down_sync(0xffffffffu, vbs, off);
            vbd += __shfl_down_sync(0xffffffffu, vbd, off);
        }
        if (lane == 0) { g_bs[0] = vbs; g_bs[1] = vbd; }
    }
}

// ---------------------------------------------------------------------------
// 2) cos = (emb @ emb^T) / (norm_i * norm_j)   64x64 tile, 4x4 per thread
__global__ __launch_bounds__(256) void cos_kernel(const float* __restrict__ emb) {
    __shared__ float As[DD][64];
    __shared__ float Bs[DD][64];
    int bi = blockIdx.y * 64;
    int bj = blockIdx.x * 64;
    int tx = threadIdx.x, ty = threadIdx.y;
    int t  = ty * 16 + tx;

    #pragma unroll
    for (int u = 0; u < 4; u++) {
        int idx = t + u * 256;
        int row = idx >> 4;
        int c4  = idx & 15;
        float4 a = *(const float4*)(emb + (bi + row) * DD + c4 * 4);
        As[c4*4+0][row] = a.x; As[c4*4+1][row] = a.y;
        As[c4*4+2][row] = a.z; As[c4*4+3][row] = a.w;
        float4 b = *(const float4*)(emb + (bj + row) * DD + c4 * 4);
        Bs[c4*4+0][row] = b.x; Bs[c4*4+1][row] = b.y;
        Bs[c4*4+2][row] = b.z; Bs[c4*4+3][row] = b.w;
    }
    __syncthreads();

    float acc[4][4];
    #pragma unroll
    for (int u = 0; u < 4; u++)
        #pragma unroll
        for (int v = 0; v < 4; v++) acc[u][v] = 0.f;

    #pragma unroll
    for (int k = 0; k < DD; k++) {
        float4 a = *(const float4*)&As[k][ty * 4];
        float4 b = *(const float4*)&Bs[k][tx * 4];
        float ar[4] = {a.x, a.y, a.z, a.w};
        float br[4] = {b.x, b.y, b.z, b.w};
        #pragma unroll
        for (int u = 0; u < 4; u++)
            #pragma unroll
            for (int v = 0; v < 4; v++) acc[u][v] += ar[u] * br[v];
    }

    float ni[4], nj[4];
    #pragma unroll
    for (int u = 0; u < 4; u++) ni[u] = g_norm[bi + ty*4 + u];
    #pragma unroll
    for (int v = 0; v < 4; v++) nj[v] = g_norm[bj + tx*4 + v];

    #pragma unroll
    for (int u = 0; u < 4; u++) {
        int i = bi + ty*4 + u;
        #pragma unroll
        for (int v = 0; v < 4; v++) {
            int j = bj + tx*4 + v;
            g_cos[(size_t)i * NN + j] = acc[u][v] / (ni[u] * nj[v]);
        }
    }
}

// ---------------------------------------------------------------------------
// 3) top-21: per-lane sort-8 (Batcher, (key desc, idx asc)) into smem, then
//    21 pops via head pointers + redux. Warp0 merges 8 sorted 21-lists.
__global__ __launch_bounds__(256) void topk_kernel() {
    __shared__ unsigned sk[2048];
    __shared__ unsigned si[2048];
    __shared__ unsigned sck[8 * KK];
    __shared__ unsigned sci[8 * KK];
    int i = blockIdx.x;
    int t = threadIdx.x, lane = t & 31, w = t >> 5;
    int base = w * 256 + lane * 8;

    const float4* row4 = (const float4*)(g_cos + (size_t)i * NN);
    float4 aa = row4[base >> 2];
    float4 bb = row4[(base >> 2) + 1];
    float v[8] = {aa.x, aa.y, aa.z, aa.w, bb.x, bb.y, bb.z, bb.w};
    unsigned kk[8], ii[8];
    #pragma unroll
    for (int q = 0; q < 8; q++) { kk[q] = fkey(v[q]); ii[q] = base + q; }

#define CAS(a,b) { bool sw = (kk[a] < kk[b]) || (kk[a] == kk[b] && ii[a] > ii[b]); \
    unsigned k1 = sw ? kk[b] : kk[a], k2 = sw ? kk[a] : kk[b]; kk[a] = k1; kk[b] = k2; \
    unsigned i1 = sw ? ii[b] : ii[a], i2 = sw ? ii[a] : ii[b]; ii[a] = i1; ii[b] = i2; }
    CAS(0,1) CAS(2,3) CAS(4,5) CAS(6,7)
    CAS(0,2) CAS(1,3) CAS(4,6) CAS(5,7)
    CAS(1,2) CAS(5,6)
    CAS(0,4) CAS(1,5) CAS(2,6) CAS(3,7)
    CAS(2,4) CAS(3,5)
    CAS(1,2) CAS(3,4) CAS(5,6)
#undef CAS

    int sb = t * 8;
    #pragma unroll
    for (int q = 0; q < 8; q++) { sk[sb + q] = kk[q]; si[sb + q] = ii[q]; }

    int hp = 0;
    #pragma unroll 1
    for (int k = 0; k < KK; k++) {
        int hc = (hp < 8) ? hp : 7;
        unsigned kcur = sk[sb + hc];
        unsigned icur = si[sb + hc];
        if (hp >= 8) kcur = 0u;
        unsigned mk = __reduce_max_sync(0xffffffffu, kcur);
        unsigned cand = (kcur == mk) ? icur : 0xffffffffu;
        unsigned wi = __reduce_min_sync(0xffffffffu, cand);
        if (lane == 0) { sck[w * KK + k] = mk; sci[w * KK + k] = wi; }
        hp += (kcur == mk && icur == wi) ? 1 : 0;
    }
    __syncthreads();

    if (w == 0) {
        bool act = lane < 8;
        int hp2 = 0;
        #pragma unroll 1
        for (int k = 0; k < KK; k++) {
            int hc = (hp2 < KK) ? hp2 : KK - 1;
            unsigned kcur = act ? sck[lane * KK + hc] : 0u;
            unsigned icur = act ? sci[lane * KK + hc] : 0xffffffffu;
            if (hp2 >= KK) kcur = 0u;
            unsigned mk = __reduce_max_sync(0xffffffffu, kcur);
            unsigned cand = (kcur == mk) ? icur : 0xffffffffu;
            unsigned wi = __reduce_min_sync(0xffffffffu, cand);
            if (lane == 0) g_idx[i * KK + k] = (int)wi;
            hp2 += (kcur == mk && icur == wi) ? 1 : 0;
        }
    }
}

// ---------------------------------------------------------------------------
// 4) h = x @ W^T + Wb -> fp16; e_src/e_dst via 5-dim dots (fp32 exact).
__global__ __launch_bounds__(256) void h2_kernel(
    const float* __restrict__ x, const float* __restrict__ W,
    const float* __restrict__ Wb) {
    __shared__ float sx[128 * TT];
    __shared__ float sW[DD * TT];
    __shared__ float sWb[DD];
    int t = threadIdx.x;
    for (int q = t; q < 128 * TT; q += 256) sx[q] = x[blockIdx.x * 128 * TT + q];
    for (int q = t; q < DD * TT; q += 256) sW[q] = W[q];
    if (t < DD) sWb[t] = Wb[t];
    __syncthreads();

    int cq = t & 15;
    int r0 = t >> 4;

    float wr[20], b4[4];
    #pragma unroll
    for (int j = 0; j < 4; j++) {
        #pragma unroll
        for (int tt = 0; tt < TT; tt++) wr[j * TT + tt] = sW[(cq * 4 + j) * TT + tt];
        b4[j] = sWb[cq * 4 + j];
    }
    float ws[TT], wd[TT];
    #pragma unroll
    for (int tt = 0; tt < TT; tt++) { ws[tt] = g_ws[tt]; wd[tt] = g_wd[tt]; }
    float bs0 = g_bs[0], bd0 = g_bs[1];

    #pragma unroll 1
    for (int g = 0; g < 8; g++) {
        int rl = g * 16 + r0;
        int row = blockIdx.x * 128 + rl;
        float xv[TT];
        #pragma unroll
        for (int tt = 0; tt < TT; tt++) xv[tt] = sx[rl * TT + tt];

        float h[4];
        #pragma unroll
        for (int j = 0; j < 4; j++) {
            float acc = b4[j];
            #pragma unroll
            for (int tt = 0; tt < TT; tt++) acc += xv[tt] * wr[j * TT + tt];
            h[j] = acc;
        }
        __half2 p0 = __floats2half2_rn(h[0], h[1]);
        __half2 p1 = __floats2half2_rn(h[2], h[3]);
        uint2 pk = make_uint2(*(unsigned*)&p0, *(unsigned*)&p1);
        *(uint2*)(g_h + ((size_t)row << 6) + cq * 4) = pk;

        if (cq == 0) {
            float es = bs0, ed = bd0;
            #pragma unroll
            for (int tt = 0; tt < TT; tt++) {
                es += xv[tt] * ws[tt];
                ed += xv[tt] * wd[tt];
            }
            int n = row & (NN - 1);
            g_esrc[row] = es + g_ces[n];
            g_edst[row] = ed + g_ced[n];
        }
    }
}

// ---------------------------------------------------------------------------
// 5) sparse attention + z*emb; warp handles 8 rows; fused BN partial sums.
//    obuf stored fp16; BN partials from fp32 register values. Deterministic.
__global__ __launch_bounds__(256) void agg_kernel(const float* __restrict__ emb) {
    __shared__ float sS[8 * 64], sQ[8 * 64];
    int t = threadIdx.x, w = t >> 5, lane = t & 31;
    int rowbase = blockIdx.x * 64 + w * 8;

    float aS0 = 0.f, aQ0 = 0.f, aS1 = 0.f, aQ1 = 0.f;

    #pragma unroll 1
    for (int r = 0; r < 8; r++) {
        int row = rowbase + r;
        int b = row >> 11;
        int i = row & (NN - 1);

        float es = g_esrc[row];
        float e = -3e38f; int j = 0;
        if (lane < KK) {
            j = g_idx[i * KK + lane];
            float vv = es + g_edst[(b << 11) + j];
            e = (vv > 0.f) ? vv : 0.2f * vv;
        }
        float m = e;
        #pragma unroll
        for (int off = 16; off; off >>= 1)
            m = fmaxf(m, __shfl_xor_sync(0xffffffffu, m, off));
        float wgt = (lane < KK) ? __expf(e - m) : 0.f;
        float s = wgt;
        #pragma unroll
        for (int off = 16; off; off >>= 1)
            s += __shfl_xor_sync(0xffffffffu, s, off);

        float z0 = 0.f, z1 = 0.f;
        #pragma unroll
        for (int k = 0; k < KK; k++) {
            float wk = __shfl_sync(0xffffffffu, wgt, k);
            int   jk = __shfl_sync(0xffffffffu, j, k);
            __half2 hh = *((const __half2*)(g_h + ((size_t)((b << 11) + jk) << 6)) + lane);
            float2 hv = __half22float2(hh);
            z0 += wk * hv.x;
            z1 += wk * hv.y;
        }
        float rs = 1.f / s;
        z0 = fmaxf(z0 * rs, 0.f);
        z1 = fmaxf(z1 * rs, 0.f);
        float2 ev = *((const float2*)(emb + i * DD) + lane);
        float o0 = z0 * ev.x, o1 = z1 * ev.y;
        *((__half2*)(g_obuf + ((size_t)row << 6)) + lane) = __floats2half2_rn(o0, o1);
        aS0 += o0; aQ0 += o0 * o0;
        aS1 += o1; aQ1 += o1 * o1;
    }

    sS[w * 64 + 2 * lane]     = aS0;
    sS[w * 64 + 2 * lane + 1] = aS1;
    sQ[w * 64 + 2 * lane]     = aQ0;
    sQ[w * 64 + 2 * lane + 1] = aQ1;
    __syncthreads();
    if (t < 64) {
        float s = 0.f, q = 0.f;
        #pragma unroll
        for (int g = 0; g < 8; g++) {
            s += sS[g * 64 + t];
            q += sQ[g * 64 + t];
        }
        g_part2[blockIdx.x * 128 + t]      = s;
        g_part2[blockIdx.x * 128 + 64 + t] = q;
    }
}

// ---------------------------------------------------------------------------
// 6) finalize mean / rsqrt(var+eps): 4 summers per channel over 1024 partials
__global__ __launch_bounds__(256) void stats_kernel() {
    __shared__ float sS[4][64], sQ[4][64];
    int t = threadIdx.x;
    int c = t & 63, g = t >> 6;
    float s = 0.f, q = 0.f;
    #pragma unroll 4
    for (int blk = g * 256; blk < (g + 1) * 256; blk++) {
        s += g_part2[blk * 128 + c];
        q += g_part2[blk * 128 + 64 + c];
    }
    sS[g][c] = s; sQ[g][c] = q;
    __syncthreads();
    if (t < 64) {
        float S = 0.f, Q = 0.f;
        #pragma unroll
        for (int gg = 0; gg < 4; gg++) { S += sS[gg][t]; Q += sQ[gg][t]; }
        float mean = S / (float)ROWS;
        float var  = Q / (float)ROWS - mean * mean;
        g_mean[t] = mean;
        g_inv[t]  = rsqrtf(var + 1e-5f);
    }
}

// ---------------------------------------------------------------------------
// 7) BN apply + relu + fc  (warp per row, half2 in, channels 2l/2l+1)
__global__ __launch_bounds__(256) void out_kernel(
    const float* __restrict__ gamma, const float* __restrict__ beta,
    const float* __restrict__ fcw, const float* __restrict__ fcb,
    float* __restrict__ out) {
    int t = threadIdx.x, w = t >> 5, lane = t & 31;
    int row = blockIdx.x * 8 + w;
    __half2 oh = *((const __half2*)(g_obuf + ((size_t)row << 6)) + lane);
    float2 o  = __half22float2(oh);
    float2 mn = *((const float2*)g_mean + lane);
    float2 iv = *((const float2*)g_inv + lane);
    float2 gm = *((const float2*)gamma + lane);
    float2 bt = *((const float2*)beta + lane);
    float2 fw = *((const float2*)fcw + lane);
    float v0 = fmaxf((o.x - mn.x) * iv.x * gm.x + bt.x, 0.f) * fw.x;
    float v1 = fmaxf((o.y - mn.y) * iv.y * gm.y + bt.y, 0.f) * fw.y;
    float acc = v0 + v1;
    #pragma unroll
    for (int off = 16; off; off >>= 1)
        acc += __shfl_down_sync(0xffffffffu, acc, off);
    if (lane == 0) out[row] = acc + fcb[0];
}

// ---------------------------------------------------------------------------
extern "C" void kernel_launch(void* const* d_in, const int* in_sizes, int n_in,
                              void* d_out, int out_size) {
    const float* x     = (const float*)d_in[0];
    const float* emb   = (const float*)d_in[1];
    const float* W     = (const float*)d_in[2];
    const float* Wb    = (const float*)d_in[3];
    const float* a_src = (const float*)d_in[4];
    const float* a_dst = (const float*)d_in[5];
    const float* gamma = (const float*)d_in[6];
    const float* beta  = (const float*)d_in[7];
    const float* fcw   = (const float*)d_in[8];
    const float* fcb   = (const float*)d_in[9];
    float* out = (float*)d_out;

    pre_kernel<<<NN/8, 256>>>(emb, W, Wb, a_src, a_dst);
    cos_kernel<<<dim3(NN/64, NN/64), dim3(16, 16)>>>(emb);
    topk_kernel<<<NN, 256>>>();
    h2_kernel<<<ROWS/128, 256>>>(x, W, Wb);
    agg_kernel<<<AGG_BLOCKS, 256>>>(emb);
    stats_kernel<<<1, 256>>>();
    out_kernel<<<ROWS/8, 256>>>(gamma, beta, fcw, fcb, out);
}

// round 12
// speedup vs baseline: 1.0349x; 1.0349x over previous
#include <cuda_runtime.h>
#include <cuda_fp16.h>
#include <math.h>

#define NN   2048
#define TT   5
#define DD   64
#define KK   21
#define BB   32
#define ROWS (BB*NN)
#define RED_BLOCKS 128

// ---- scratch (device globals; no runtime allocation) ----
__device__ float  g_cos[NN*NN];      // 16 MB
__device__ float  g_ces[NN];         // emb . a_src[64:]
__device__ float  g_ced[NN];         // emb . a_dst[64:]
__device__ float  g_ws[TT];          // W^T a_src[:64]
__device__ float  g_wd[TT];
__device__ float  g_bs[2];           // Wb.a_src[:64], Wb.a_dst[:64]
__device__ int    g_idx[NN*KK];
__device__ __half g_h[ROWS*DD];      // 8 MB (fp16; only consumer is agg gather)
__device__ float  g_esrc[ROWS];
__device__ float  g_edst[ROWS];
__device__ __half g_obuf[ROWS*DD];   // 8 MB (fp16)
__device__ float  g_part[RED_BLOCKS*128];
__device__ float  g_mean[DD];
__device__ float  g_inv[DD];

// monotonic float->uint key (total order matches float >)
__device__ __forceinline__ unsigned fkey(float f) {
    unsigned b = __float_as_uint(f);
    return (b & 0x80000000u) ? ~b : (b | 0x80000000u);
}

// ---------------------------------------------------------------------------
// 1) cos = (emb @ emb^T) / (norm_i * norm_j)   64x64 tile, 4x4 per thread;
//    norms computed inline in smem (no pre pass).
__global__ __launch_bounds__(256) void cos_kernel(const float* __restrict__ emb) {
    __shared__ float As[DD][64];
    __shared__ float Bs[DD][64];
    __shared__ float nI[64], nJ[64];
    int bi = blockIdx.y * 64;
    int bj = blockIdx.x * 64;
    int tx = threadIdx.x, ty = threadIdx.y;
    int t  = ty * 16 + tx;

    #pragma unroll
    for (int u = 0; u < 4; u++) {
        int idx = t + u * 256;
        int row = idx >> 4;
        int c4  = idx & 15;
        float4 a = *(const float4*)(emb + (bi + row) * DD + c4 * 4);
        As[c4*4+0][row] = a.x; As[c4*4+1][row] = a.y;
        As[c4*4+2][row] = a.z; As[c4*4+3][row] = a.w;
        float4 b = *(const float4*)(emb + (bj + row) * DD + c4 * 4);
        Bs[c4*4+0][row] = b.x; Bs[c4*4+1][row] = b.y;
        Bs[c4*4+2][row] = b.z; Bs[c4*4+3][row] = b.w;
    }
    if (t < 128) {
        int row = (t < 64) ? (bi + t) : (bj + t - 64);
        const float4* p = (const float4*)(emb + row * DD);
        float s = 0.f;
        #pragma unroll
        for (int q = 0; q < 16; q++) {
            float4 v = p[q];
            s += v.x*v.x + v.y*v.y + v.z*v.z + v.w*v.w;
        }
        if (t < 64) nI[t] = sqrtf(s); else nJ[t - 64] = sqrtf(s);
    }
    __syncthreads();

    float acc[4][4];
    #pragma unroll
    for (int u = 0; u < 4; u++)
        #pragma unroll
        for (int v = 0; v < 4; v++) acc[u][v] = 0.f;

    #pragma unroll
    for (int k = 0; k < DD; k++) {
        float4 a = *(const float4*)&As[k][ty * 4];
        float4 b = *(const float4*)&Bs[k][tx * 4];
        float ar[4] = {a.x, a.y, a.z, a.w};
        float br[4] = {b.x, b.y, b.z, b.w};
        #pragma unroll
        for (int u = 0; u < 4; u++)
            #pragma unroll
            for (int v = 0; v < 4; v++) acc[u][v] += ar[u] * br[v];
    }

    float ni[4], nj[4];
    #pragma unroll
    for (int u = 0; u < 4; u++) ni[u] = nI[ty*4 + u];
    #pragma unroll
    for (int v = 0; v < 4; v++) nj[v] = nJ[tx*4 + v];

    #pragma unroll
    for (int u = 0; u < 4; u++) {
        int i = bi + ty*4 + u;
        #pragma unroll
        for (int v = 0; v < 4; v++) {
            int j = bj + tx*4 + v;
            g_cos[(size_t)i * NN + j] = acc[u][v] / (ni[u] * nj[v]);
        }
    }
}

// ---------------------------------------------------------------------------
// 2) top-21 + per-node attention constants. Block i = node i.
//    Phase1: per-lane sort-8 (Batcher), 21 pops via redux. Warp0 merges;
//    warp1 computes ces/ced for node i; warp2 (block 0) computes ws/wd/bs.
__global__ __launch_bounds__(256) void topk_kernel(
    const float* __restrict__ emb, const float* __restrict__ W,
    const float* __restrict__ Wb,
    const float* __restrict__ a_src, const float* __restrict__ a_dst) {
    __shared__ unsigned sk[2048];
    __shared__ unsigned si[2048];
    __shared__ unsigned sck[8 * KK];
    __shared__ unsigned sci[8 * KK];
    int i = blockIdx.x;
    int t = threadIdx.x, lane = t & 31, w = t >> 5;
    int base = w * 256 + lane * 8;

    const float4* row4 = (const float4*)(g_cos + (size_t)i * NN);
    float4 aa = row4[base >> 2];
    float4 bb = row4[(base >> 2) + 1];
    float v[8] = {aa.x, aa.y, aa.z, aa.w, bb.x, bb.y, bb.z, bb.w};
    unsigned kk[8], ii[8];
    #pragma unroll
    for (int q = 0; q < 8; q++) { kk[q] = fkey(v[q]); ii[q] = base + q; }

#define CAS(a,b) { bool sw = (kk[a] < kk[b]) || (kk[a] == kk[b] && ii[a] > ii[b]); \
    unsigned k1 = sw ? kk[b] : kk[a], k2 = sw ? kk[a] : kk[b]; kk[a] = k1; kk[b] = k2; \
    unsigned i1 = sw ? ii[b] : ii[a], i2 = sw ? ii[a] : ii[b]; ii[a] = i1; ii[b] = i2; }
    CAS(0,1) CAS(2,3) CAS(4,5) CAS(6,7)
    CAS(0,2) CAS(1,3) CAS(4,6) CAS(5,7)
    CAS(1,2) CAS(5,6)
    CAS(0,4) CAS(1,5) CAS(2,6) CAS(3,7)
    CAS(2,4) CAS(3,5)
    CAS(1,2) CAS(3,4) CAS(5,6)
#undef CAS

    int sb = t * 8;
    #pragma unroll
    for (int q = 0; q < 8; q++) { sk[sb + q] = kk[q]; si[sb + q] = ii[q]; }

    int hp = 0;
    #pragma unroll 1
    for (int k = 0; k < KK; k++) {
        int hc = (hp < 8) ? hp : 7;
        unsigned kcur = sk[sb + hc];
        unsigned icur = si[sb + hc];
        if (hp >= 8) kcur = 0u;
        unsigned mk = __reduce_max_sync(0xffffffffu, kcur);
        unsigned cand = (kcur == mk) ? icur : 0xffffffffu;
        unsigned wi = __reduce_min_sync(0xffffffffu, cand);
        if (lane == 0) { sck[w * KK + k] = mk; sci[w * KK + k] = wi; }
        hp += (kcur == mk && icur == wi) ? 1 : 0;
    }
    __syncthreads();

    if (w == 0) {
        bool act = lane < 8;
        int hp2 = 0;
        #pragma unroll 1
        for (int k = 0; k < KK; k++) {
            int hc = (hp2 < KK) ? hp2 : KK - 1;
            unsigned kcur = act ? sck[lane * KK + hc] : 0u;
            unsigned icur = act ? sci[lane * KK + hc] : 0xffffffffu;
            if (hp2 >= KK) kcur = 0u;
            unsigned mk = __reduce_max_sync(0xffffffffu, kcur);
            unsigned cand = (kcur == mk) ? icur : 0xffffffffu;
            unsigned wi = __reduce_min_sync(0xffffffffu, cand);
            if (lane == 0) g_idx[i * KK + k] = (int)wi;
            hp2 += (kcur == mk && icur == wi) ? 1 : 0;
        }
    } else if (w == 1) {
        // per-node emb-attention constants (node i)
        float e0 = emb[i * DD + lane], e1 = emb[i * DD + lane + 32];
        float ps = e0 * a_src[DD + lane] + e1 * a_src[DD + lane + 32];
        float pd = e0 * a_dst[DD + lane] + e1 * a_dst[DD + lane + 32];
        #pragma unroll
        for (int off = 16; off; off >>= 1) {
            ps += __shfl_down_sync(0xffffffffu, ps, off);
            pd += __shfl_down_sync(0xffffffffu, pd, off);
        }
        if (lane == 0) { g_ces[i] = ps; g_ced[i] = pd; }
    } else if (w == 2 && i == 0) {
        // projected 5-dim attention weights (once)
        float a0 = a_src[lane], a1 = a_src[lane + 32];
        float d0 = a_dst[lane], d1 = a_dst[lane + 32];
        #pragma unroll
        for (int tt = 0; tt < TT; tt++) {
            float w0 = W[lane * TT + tt], w1 = W[(lane + 32) * TT + tt];
            float vs = w0 * a0 + w1 * a1;
            float vd = w0 * d0 + w1 * d1;
            #pragma unroll
            for (int off = 16; off; off >>= 1) {
                vs += __shfl_down_sync(0xffffffffu, vs, off);
                vd += __shfl_down_sync(0xffffffffu, vd, off);
            }
            if (lane == 0) { g_ws[tt] = vs; g_wd[tt] = vd; }
        }
        float b0 = Wb[lane], b1 = Wb[lane + 32];
        float vbs = b0 * a0 + b1 * a1;
        float vbd = b0 * d0 + b1 * d1;
        #pragma unroll
        for (int off = 16; off; off >>= 1) {
            vbs += __shfl_down_sync(0xffffffffu, vbs, off);
            vbd += __shfl_down_sync(0xffffffffu, vbd, off);
        }
        if (lane == 0) { g_bs[0] = vbs; g_bs[1] = vbd; }
    }
}

// ---------------------------------------------------------------------------
// 3) h = x @ W^T + Wb -> fp16; e_src/e_dst via 5-dim dots (fp32 exact).
__global__ __launch_bounds__(256) void h2_kernel(
    const float* __restrict__ x, const float* __restrict__ W,
    const float* __restrict__ Wb) {
    __shared__ float sx[128 * TT];
    __shared__ float sW[DD * TT];
    __shared__ float sWb[DD];
    int t = threadIdx.x;
    for (int q = t; q < 128 * TT; q += 256) sx[q] = x[blockIdx.x * 128 * TT + q];
    for (int q = t; q < DD * TT; q += 256) sW[q] = W[q];
    if (t < DD) sWb[t] = Wb[t];
    __syncthreads();

    int cq = t & 15;
    int r0 = t >> 4;

    float wr[20], b4[4];
    #pragma unroll
    for (int j = 0; j < 4; j++) {
        #pragma unroll
        for (int tt = 0; tt < TT; tt++) wr[j * TT + tt] = sW[(cq * 4 + j) * TT + tt];
        b4[j] = sWb[cq * 4 + j];
    }
    float ws[TT], wd[TT];
    #pragma unroll
    for (int tt = 0; tt < TT; tt++) { ws[tt] = g_ws[tt]; wd[tt] = g_wd[tt]; }
    float bs0 = g_bs[0], bd0 = g_bs[1];

    #pragma unroll 1
    for (int g = 0; g < 8; g++) {
        int rl = g * 16 + r0;
        int row = blockIdx.x * 128 + rl;
        float xv[TT];
        #pragma unroll
        for (int tt = 0; tt < TT; tt++) xv[tt] = sx[rl * TT + tt];

        float h[4];
        #pragma unroll
        for (int j = 0; j < 4; j++) {
            float acc = b4[j];
            #pragma unroll
            for (int tt = 0; tt < TT; tt++) acc += xv[tt] * wr[j * TT + tt];
            h[j] = acc;
        }
        __half2 p0 = __floats2half2_rn(h[0], h[1]);
        __half2 p1 = __floats2half2_rn(h[2], h[3]);
        uint2 pk = make_uint2(*(unsigned*)&p0, *(unsigned*)&p1);
        *(uint2*)(g_h + ((size_t)row << 6) + cq * 4) = pk;

        if (cq == 0) {
            float es = bs0, ed = bd0;
            #pragma unroll
            for (int tt = 0; tt < TT; tt++) {
                es += xv[tt] * ws[tt];
                ed += xv[tt] * wd[tt];
            }
            int n = row & (NN - 1);
            g_esrc[row] = es + g_ces[n];
            g_edst[row] = ed + g_ced[n];
        }
    }
}

// ---------------------------------------------------------------------------
// 4) sparse attention + z*emb (warp per row; half2 gathers; half2 store)
__global__ __launch_bounds__(256) void agg_kernel(const float* __restrict__ emb) {
    int t = threadIdx.x, w = t >> 5, lane = t & 31;
    int row = blockIdx.x * 8 + w;
    int b = row >> 11;
    int i = row & (NN - 1);

    float es = g_esrc[row];
    float e = -3e38f; int j = 0;
    if (lane < KK) {
        j = g_idx[i * KK + lane];
        float v = es + g_edst[(b << 11) + j];
        e = (v > 0.f) ? v : 0.2f * v;
    }
    float m = e;
    #pragma unroll
    for (int off = 16; off; off >>= 1)
        m = fmaxf(m, __shfl_xor_sync(0xffffffffu, m, off));
    float wgt = (lane < KK) ? __expf(e - m) : 0.f;
    float s = wgt;
    #pragma unroll
    for (int off = 16; off; off >>= 1)
        s += __shfl_xor_sync(0xffffffffu, s, off);

    float z0 = 0.f, z1 = 0.f;
    #pragma unroll
    for (int k = 0; k < KK; k++) {
        float wk = __shfl_sync(0xffffffffu, wgt, k);
        int   jk = __shfl_sync(0xffffffffu, j, k);
        __half2 hh = *((const __half2*)(g_h + ((size_t)((b << 11) + jk) << 6)) + lane);
        float2 hv = __half22float2(hh);
        z0 += wk * hv.x;
        z1 += wk * hv.y;
    }
    float rs = 1.f / s;
    z0 = fmaxf(z0 * rs, 0.f);
    z1 = fmaxf(z1 * rs, 0.f);
    float2 ev = *((const float2*)(emb + i * DD) + lane);
    *((__half2*)(g_obuf + ((size_t)row << 6)) + lane) =
        __floats2half2_rn(z0 * ev.x, z1 * ev.y);
}

// ---------------------------------------------------------------------------
// 5) BN stats partial reduce over fp16 obuf (uint4 = 8 halves per thread;
//    thread t owns channels 8*(t&7)..+7; deterministic regroup)
__global__ __launch_bounds__(256) void red_kernel() {
    __shared__ float ss[256 * 8], sq[256 * 8];
    int t = threadIdx.x;
    int gt = blockIdx.x * 256 + t;
    const uint4* p = (const uint4*)g_obuf;
    float s[8], q[8];
    #pragma unroll
    for (int jj = 0; jj < 8; jj++) { s[jj] = 0.f; q[jj] = 0.f; }
    const int total = ROWS * DD / 8;           // 524288 uint4
    for (int idx = gt; idx < total; idx += RED_BLOCKS * 256) {
        uint4 v = p[idx];
        float2 f0 = __half22float2(*(__half2*)&v.x);
        float2 f1 = __half22float2(*(__half2*)&v.y);
        float2 f2 = __half22float2(*(__half2*)&v.z);
        float2 f3 = __half22float2(*(__half2*)&v.w);
        s[0] += f0.x; q[0] += f0.x * f0.x;
        s[1] += f0.y; q[1] += f0.y * f0.y;
        s[2] += f1.x; q[2] += f1.x * f1.x;
        s[3] += f1.y; q[3] += f1.y * f1.y;
        s[4] += f2.x; q[4] += f2.x * f2.x;
        s[5] += f2.y; q[5] += f2.y * f2.y;
        s[6] += f3.x; q[6] += f3.x * f3.x;
        s[7] += f3.y; q[7] += f3.y * f3.y;
    }
    #pragma unroll
    for (int jj = 0; jj < 8; jj++) { ss[t * 8 + jj] = s[jj]; sq[t * 8 + jj] = q[jj]; }
    __syncthreads();
    if (t < DD) {
        // channel t: owner threads thr = (t>>3) + 8k hold it at slot (t&7)
        float a = 0.f, b2 = 0.f;
        #pragma unroll 8
        for (int k = 0; k < 32; k++) {
            int thr = (t >> 3) + 8 * k;
            a  += ss[thr * 8 + (t & 7)];
            b2 += sq[thr * 8 + (t & 7)];
        }
        g_part[blockIdx.x * 128 + t]      = a;
        g_part[blockIdx.x * 128 + 64 + t] = b2;
    }
}

// 6) finalize mean / rsqrt(var+eps)
__global__ void stats_kernel() {
    int c = threadIdx.x;  // 64
    float s = 0.f, s2 = 0.f;
    for (int bk = 0; bk < RED_BLOCKS; bk++) {
        s  += g_part[bk * 128 + c];
        s2 += g_part[bk * 128 + 64 + c];
    }
    float mean = s / (float)ROWS;
    float var  = s2 / (float)ROWS - mean * mean;
    g_mean[c] = mean;
    g_inv[c]  = rsqrtf(var + 1e-5f);
}

// ---------------------------------------------------------------------------
// 7) BN apply + relu + fc  (warp per row, half2 in, channels 2l/2l+1)
__global__ __launch_bounds__(256) void out_kernel(
    const float* __restrict__ gamma, const float* __restrict__ beta,
    const float* __restrict__ fcw, const float* __restrict__ fcb,
    float* __restrict__ out) {
    int t = threadIdx.x, w = t >> 5, lane = t & 31;
    int row = blockIdx.x * 8 + w;
    __half2 oh = *((const __half2*)(g_obuf + ((size_t)row << 6)) + lane);
    float2 o  = __half22float2(oh);
    float2 mn = *((const float2*)g_mean + lane);
    float2 iv = *((const float2*)g_inv + lane);
    float2 gm = *((const float2*)gamma + lane);
    float2 bt = *((const float2*)beta + lane);
    float2 fw = *((const float2*)fcw + lane);
    float v0 = fmaxf((o.x - mn.x) * iv.x * gm.x + bt.x, 0.f) * fw.x;
    float v1 = fmaxf((o.y - mn.y) * iv.y * gm.y + bt.y, 0.f) * fw.y;
    float acc = v0 + v1;
    #pragma unroll
    for (int off = 16; off; off >>= 1)
        acc += __shfl_down_sync(0xffffffffu, acc, off);
    if (lane == 0) out[row] = acc + fcb[0];
}

// ---------------------------------------------------------------------------
extern "C" void kernel_launch(void* const* d_in, const int* in_sizes, int n_in,
                              void* d_out, int out_size) {
    const float* x     = (const float*)d_in[0];
    const float* emb   = (const float*)d_in[1];
    const float* W     = (const float*)d_in[2];
    const float* Wb    = (const float*)d_in[3];
    const float* a_src = (const float*)d_in[4];
    const float* a_dst = (const float*)d_in[5];
    const float* gamma = (const float*)d_in[6];
    const float* beta  = (const float*)d_in[7];
    const float* fcw   = (const float*)d_in[8];
    const float* fcb   = (const float*)d_in[9];
    float* out = (float*)d_out;

    cos_kernel<<<dim3(NN/64, NN/64), dim3(16, 16)>>>(emb);
    topk_kernel<<<NN, 256>>>(emb, W, Wb, a_src, a_dst);
    h2_kernel<<<ROWS/128, 256>>>(x, W, Wb);
    agg_kernel<<<ROWS/8, 256>>>(emb);
    red_kernel<<<RED_BLOCKS, 256>>>();
    stats_kernel<<<1, 64>>>();
    out_kernel<<<ROWS/8, 256>>>(gamma, beta, fcw, fcb, out);
}

// round 14
// speedup vs baseline: 1.1022x; 1.0650x over previous
#include <cuda_runtime.h>
#include <cuda_fp16.h>
#include <math.h>

#define NN   2048
#define TT   5
#define DD   64
#define KK   21
#define BB   32
#define ROWS (BB*NN)
#define RED_BLOCKS 128

// ---- scratch (device globals; no runtime allocation) ----
__device__ float  g_cos[NN*NN];      // 16 MB
__device__ float  g_norm[NN];
__device__ float  g_ces[NN];         // emb . a_src[64:]
__device__ float  g_ced[NN];         // emb . a_dst[64:]
__device__ float  g_ws[TT];          // W^T a_src[:64]
__device__ float  g_wd[TT];
__device__ float  g_bs[2];           // Wb.a_src[:64], Wb.a_dst[:64]
__device__ int    g_idx[NN*KK];
__device__ __half g_h[ROWS*DD];      // 8 MB (fp16; only consumer is agg gather)
__device__ float  g_esrc[ROWS];
__device__ float  g_edst[ROWS];
__device__ __half g_obuf[ROWS*DD];   // 8 MB (fp16)
__device__ float  g_part[RED_BLOCKS*128];
__device__ float  g_mean[DD];
__device__ float  g_inv[DD];

// monotonic float->uint key (total order matches float >)
__device__ __forceinline__ unsigned fkey(float f) {
    unsigned b = __float_as_uint(f);
    return (b & 0x80000000u) ? ~b : (b | 0x80000000u);
}

// ---------------------------------------------------------------------------
// 1) pre: per-node norms + emb-attention constants; warp 0 of block 0 also
//    computes the 5-dim projected attention weights.
__global__ __launch_bounds__(256) void pre_kernel(
    const float* __restrict__ emb, const float* __restrict__ W,
    const float* __restrict__ Wb,
    const float* __restrict__ a_src, const float* __restrict__ a_dst) {
    int t = threadIdx.x, lane = t & 31, w = t >> 5;
    int n = blockIdx.x * 8 + w;

    float e0 = emb[n * DD + lane], e1 = emb[n * DD + lane + 32];
    float s  = e0 * e0 + e1 * e1;
    float ps = e0 * a_src[DD + lane] + e1 * a_src[DD + lane + 32];
    float pd = e0 * a_dst[DD + lane] + e1 * a_dst[DD + lane + 32];
    #pragma unroll
    for (int off = 16; off; off >>= 1) {
        s  += __shfl_down_sync(0xffffffffu, s, off);
        ps += __shfl_down_sync(0xffffffffu, ps, off);
        pd += __shfl_down_sync(0xffffffffu, pd, off);
    }
    if (lane == 0) {
        g_norm[n] = sqrtf(s);
        g_ces[n] = ps;
        g_ced[n] = pd;
    }

    if (blockIdx.x == 0 && w == 0) {
        float a0 = a_src[lane], a1 = a_src[lane + 32];
        float d0 = a_dst[lane], d1 = a_dst[lane + 32];
        #pragma unroll
        for (int tt = 0; tt < TT; tt++) {
            float w0 = W[lane * TT + tt], w1 = W[(lane + 32) * TT + tt];
            float vs = w0 * a0 + w1 * a1;
            float vd = w0 * d0 + w1 * d1;
            #pragma unroll
            for (int off = 16; off; off >>= 1) {
                vs += __shfl_down_sync(0xffffffffu, vs, off);
                vd += __shfl_down_sync(0xffffffffu, vd, off);
            }
            if (lane == 0) { g_ws[tt] = vs; g_wd[tt] = vd; }
        }
        float b0 = Wb[lane], b1 = Wb[lane + 32];
        float vbs = b0 * a0 + b1 * a1;
        float vbd = b0 * d0 + b1 * d1;
        #pragma unroll
        for (int off = 16; off; off >>= 1) {
            vbs += __shfl_down_sync(0xffffffffu, vbs, off);
            vbd += __shfl_down_sync(0xffffffffu, vbd, off);
        }
        if (lane == 0) { g_bs[0] = vbs; g_bs[1] = vbd; }
    }
}

// ---------------------------------------------------------------------------
// 2) cos = (emb @ emb^T) / (norm_i * norm_j)   64x64 tile, 4x4 per thread
__global__ __launch_bounds__(256) void cos_kernel(const float* __restrict__ emb) {
    __shared__ float As[DD][64];
    __shared__ float Bs[DD][64];
    int bi = blockIdx.y * 64;
    int bj = blockIdx.x * 64;
    int tx = threadIdx.x, ty = threadIdx.y;
    int t  = ty * 16 + tx;

    #pragma unroll
    for (int u = 0; u < 4; u++) {
        int idx = t + u * 256;
        int row = idx >> 4;
        int c4  = idx & 15;
        float4 a = *(const float4*)(emb + (bi + row) * DD + c4 * 4);
        As[c4*4+0][row] = a.x; As[c4*4+1][row] = a.y;
        As[c4*4+2][row] = a.z; As[c4*4+3][row] = a.w;
        float4 b = *(const float4*)(emb + (bj + row) * DD + c4 * 4);
        Bs[c4*4+0][row] = b.x; Bs[c4*4+1][row] = b.y;
        Bs[c4*4+2][row] = b.z; Bs[c4*4+3][row] = b.w;
    }
    __syncthreads();

    float acc[4][4];
    #pragma unroll
    for (int u = 0; u < 4; u++)
        #pragma unroll
        for (int v = 0; v < 4; v++) acc[u][v] = 0.f;

    #pragma unroll
    for (int k = 0; k < DD; k++) {
        float4 a = *(const float4*)&As[k][ty * 4];
        float4 b = *(const float4*)&Bs[k][tx * 4];
        float ar[4] = {a.x, a.y, a.z, a.w};
        float br[4] = {b.x, b.y, b.z, b.w};
        #pragma unroll
        for (int u = 0; u < 4; u++)
            #pragma unroll
            for (int v = 0; v < 4; v++) acc[u][v] += ar[u] * br[v];
    }

    float ni[4], nj[4];
    #pragma unroll
    for (int u = 0; u < 4; u++) ni[u] = g_norm[bi + ty*4 + u];
    #pragma unroll
    for (int v = 0; v < 4; v++) nj[v] = g_norm[bj + tx*4 + v];

    #pragma unroll
    for (int u = 0; u < 4; u++) {
        int i = bi + ty*4 + u;
        #pragma unroll
        for (int v = 0; v < 4; v++) {
            int j = bj + tx*4 + v;
            g_cos[(size_t)i * NN + j] = acc[u][v] / (ni[u] * nj[v]);
        }
    }
}

// ---------------------------------------------------------------------------
// 3) top-21: per-lane sort-8 (Batcher, (key desc, idx asc)) into smem, then
//    21 pops via head pointers + redux. Warp0 merges 8 sorted 21-lists.
__global__ __launch_bounds__(256) void topk_kernel() {
    __shared__ unsigned sk[2048];
    __shared__ unsigned si[2048];
    __shared__ unsigned sck[8 * KK];
    __shared__ unsigned sci[8 * KK];
    int i = blockIdx.x;
    int t = threadIdx.x, lane = t & 31, w = t >> 5;
    int base = w * 256 + lane * 8;

    const float4* row4 = (const float4*)(g_cos + (size_t)i * NN);
    float4 aa = row4[base >> 2];
    float4 bb = row4[(base >> 2) + 1];
    float v[8] = {aa.x, aa.y, aa.z, aa.w, bb.x, bb.y, bb.z, bb.w};
    unsigned kk[8], ii[8];
    #pragma unroll
    for (int q = 0; q < 8; q++) { kk[q] = fkey(v[q]); ii[q] = base + q; }

#define CAS(a,b) { bool sw = (kk[a] < kk[b]) || (kk[a] == kk[b] && ii[a] > ii[b]); \
    unsigned k1 = sw ? kk[b] : kk[a], k2 = sw ? kk[a] : kk[b]; kk[a] = k1; kk[b] = k2; \
    unsigned i1 = sw ? ii[b] : ii[a], i2 = sw ? ii[a] : ii[b]; ii[a] = i1; ii[b] = i2; }
    CAS(0,1) CAS(2,3) CAS(4,5) CAS(6,7)
    CAS(0,2) CAS(1,3) CAS(4,6) CAS(5,7)
    CAS(1,2) CAS(5,6)
    CAS(0,4) CAS(1,5) CAS(2,6) CAS(3,7)
    CAS(2,4) CAS(3,5)
    CAS(1,2) CAS(3,4) CAS(5,6)
#undef CAS

    int sb = t * 8;
    #pragma unroll
    for (int q = 0; q < 8; q++) { sk[sb + q] = kk[q]; si[sb + q] = ii[q]; }

    int hp = 0;
    #pragma unroll 1
    for (int k = 0; k < KK; k++) {
        int hc = (hp < 8) ? hp : 7;
        unsigned kcur = sk[sb + hc];
        unsigned icur = si[sb + hc];
        if (hp >= 8) kcur = 0u;
        unsigned mk = __reduce_max_sync(0xffffffffu, kcur);
        unsigned cand = (kcur == mk) ? icur : 0xffffffffu;
        unsigned wi = __reduce_min_sync(0xffffffffu, cand);
        if (lane == 0) { sck[w * KK + k] = mk; sci[w * KK + k] = wi; }
        hp += (kcur == mk && icur == wi) ? 1 : 0;
    }
    __syncthreads();

    if (w == 0) {
        bool act = lane < 8;
        int hp2 = 0;
        #pragma unroll 1
        for (int k = 0; k < KK; k++) {
            int hc = (hp2 < KK) ? hp2 : KK - 1;
            unsigned kcur = act ? sck[lane * KK + hc] : 0u;
            unsigned icur = act ? sci[lane * KK + hc] : 0xffffffffu;
            if (hp2 >= KK) kcur = 0u;
            unsigned mk = __reduce_max_sync(0xffffffffu, kcur);
            unsigned cand = (kcur == mk) ? icur : 0xffffffffu;
            unsigned wi = __reduce_min_sync(0xffffffffu, cand);
            if (lane == 0) g_idx[i * KK + k] = (int)wi;
            hp2 += (kcur == mk && icur == wi) ? 1 : 0;
        }
    }
}

// ---------------------------------------------------------------------------
// 4) h = x @ W^T + Wb -> fp16; e_src/e_dst via 5-dim dots (fp32 exact).
__global__ __launch_bounds__(256) void h2_kernel(
    const float* __restrict__ x, const float* __restrict__ W,
    const float* __restrict__ Wb) {
    __shared__ float sx[128 * TT];
    __shared__ float sW[DD * TT];
    __shared__ float sWb[DD];
    int t = threadIdx.x;
    for (int q = t; q < 128 * TT; q += 256) sx[q] = x[blockIdx.x * 128 * TT + q];
    for (int q = t; q < DD * TT; q += 256) sW[q] = W[q];
    if (t < DD) sWb[t] = Wb[t];
    __syncthreads();

    int cq = t & 15;
    int r0 = t >> 4;

    float wr[20], b4[4];
    #pragma unroll
    for (int j = 0; j < 4; j++) {
        #pragma unroll
        for (int tt = 0; tt < TT; tt++) wr[j * TT + tt] = sW[(cq * 4 + j) * TT + tt];
        b4[j] = sWb[cq * 4 + j];
    }
    float ws[TT], wd[TT];
    #pragma unroll
    for (int tt = 0; tt < TT; tt++) { ws[tt] = g_ws[tt]; wd[tt] = g_wd[tt]; }
    float bs0 = g_bs[0], bd0 = g_bs[1];

    #pragma unroll 1
    for (int g = 0; g < 8; g++) {
        int rl = g * 16 + r0;
        int row = blockIdx.x * 128 + rl;
        float xv[TT];
        #pragma unroll
        for (int tt = 0; tt < TT; tt++) xv[tt] = sx[rl * TT + tt];

        float h[4];
        #pragma unroll
        for (int j = 0; j < 4; j++) {
            float acc = b4[j];
            #pragma unroll
            for (int tt = 0; tt < TT; tt++) acc += xv[tt] * wr[j * TT + tt];
            h[j] = acc;
        }
        __half2 p0 = __floats2half2_rn(h[0], h[1]);
        __half2 p1 = __floats2half2_rn(h[2], h[3]);
        uint2 pk = make_uint2(*(unsigned*)&p0, *(unsigned*)&p1);
        *(uint2*)(g_h + ((size_t)row << 6) + cq * 4) = pk;

        if (cq == 0) {
            float es = bs0, ed = bd0;
            #pragma unroll
            for (int tt = 0; tt < TT; tt++) {
                es += xv[tt] * ws[tt];
                ed += xv[tt] * wd[tt];
            }
            int n = row & (NN - 1);
            g_esrc[row] = es + g_ces[n];
            g_edst[row] = ed + g_ced[n];
        }
    }
}

// ---------------------------------------------------------------------------
// 5) sparse attention + z*emb (warp per row; half2 gathers; fp16 store)
__global__ __launch_bounds__(256) void agg_kernel(const float* __restrict__ emb) {
    int t = threadIdx.x, w = t >> 5, lane = t & 31;
    int row = blockIdx.x * 8 + w;
    int b = row >> 11;
    int i = row & (NN - 1);

    float es = g_esrc[row];
    float e = -3e38f; int j = 0;
    if (lane < KK) {
        j = g_idx[i * KK + lane];
        float v = es + g_edst[(b << 11) + j];
        e = (v > 0.f) ? v : 0.2f * v;
    }
    float m = e;
    #pragma unroll
    for (int off = 16; off; off >>= 1)
        m = fmaxf(m, __shfl_xor_sync(0xffffffffu, m, off));
    float wgt = (lane < KK) ? __expf(e - m) : 0.f;
    float s = wgt;
    #pragma unroll
    for (int off = 16; off; off >>= 1)
        s += __shfl_xor_sync(0xffffffffu, s, off);

    float z0 = 0.f, z1 = 0.f;
    #pragma unroll
    for (int k = 0; k < KK; k++) {
        float wk = __shfl_sync(0xffffffffu, wgt, k);
        int   jk = __shfl_sync(0xffffffffu, j, k);
        __half2 hh = *((const __half2*)(g_h + ((size_t)((b << 11) + jk) << 6)) + lane);
        float2 hv = __half22float2(hh);
        z0 += wk * hv.x;
        z1 += wk * hv.y;
    }
    float rs = 1.f / s;
    z0 = fmaxf(z0 * rs, 0.f);
    z1 = fmaxf(z1 * rs, 0.f);
    float2 ev = *((const float2*)(emb + i * DD) + lane);
    *((__half2*)(g_obuf + ((size_t)row << 6)) + lane) =
        __floats2half2_rn(z0 * ev.x, z1 * ev.y);
}

// ---------------------------------------------------------------------------
// 6) BN stats partial reduce over fp16 obuf (uint4 = 8 halves per thread;
//    thread t owns channels 8*(t&7)..+7; deterministic regroup, addr ≡ t+64k)
__global__ __launch_bounds__(256) void red_kernel() {
    __shared__ float ss[256 * 8], sq[256 * 8];
    int t = threadIdx.x;
    int gt = blockIdx.x * 256 + t;
    const uint4* p = (const uint4*)g_obuf;
    float s[8], q[8];
    #pragma unroll
    for (int jj = 0; jj < 8; jj++) { s[jj] = 0.f; q[jj] = 0.f; }
    const int total = ROWS * DD / 8;           // 524288 uint4
    for (int idx = gt; idx < total; idx += RED_BLOCKS * 256) {
        uint4 v = p[idx];
        float2 f0 = __half22float2(*(__half2*)&v.x);
        float2 f1 = __half22float2(*(__half2*)&v.y);
        float2 f2 = __half22float2(*(__half2*)&v.z);
        float2 f3 = __half22float2(*(__half2*)&v.w);
        s[0] += f0.x; q[0] += f0.x * f0.x;
        s[1] += f0.y; q[1] += f0.y * f0.y;
        s[2] += f1.x; q[2] += f1.x * f1.x;
        s[3] += f1.y; q[3] += f1.y * f1.y;
        s[4] += f2.x; q[4] += f2.x * f2.x;
        s[5] += f2.y; q[5] += f2.y * f2.y;
        s[6] += f3.x; q[6] += f3.x * f3.x;
        s[7] += f3.y; q[7] += f3.y * f3.y;
    }
    #pragma unroll
    for (int jj = 0; jj < 8; jj++) { ss[t * 8 + jj] = s[jj]; sq[t * 8 + jj] = q[jj]; }
    __syncthreads();
    if (t < DD) {
        float a = 0.f, b2 = 0.f;
        #pragma unroll 8
        for (int k = 0; k < 32; k++) {
            int thr = (t >> 3) + 8 * k;
            a  += ss[thr * 8 + (t & 7)];
            b2 += sq[thr * 8 + (t & 7)];
        }
        g_part[blockIdx.x * 128 + t]      = a;
        g_part[blockIdx.x * 128 + 64 + t] = b2;
    }
}

// 7) finalize mean / rsqrt(var+eps)
__global__ void stats_kernel() {
    int c = threadIdx.x;  // 64
    float s = 0.f, s2 = 0.f;
    for (int bk = 0; bk < RED_BLOCKS; bk++) {
        s  += g_part[bk * 128 + c];
        s2 += g_part[bk * 128 + 64 + c];
    }
    float mean = s / (float)ROWS;
    float var  = s2 / (float)ROWS - mean * mean;
    g_mean[c] = mean;
    g_inv[c]  = rsqrtf(var + 1e-5f);
}

// ---------------------------------------------------------------------------
// 8) BN apply + relu + fc  (warp per row, half2 in, channels 2l/2l+1)
__global__ __launch_bounds__(256) void out_kernel(
    const float* __restrict__ gamma, const float* __restrict__ beta,
    const float* __restrict__ fcw, const float* __restrict__ fcb,
    float* __restrict__ out) {
    int t = threadIdx.x, w = t >> 5, lane = t & 31;
    int row = blockIdx.x * 8 + w;
    __half2 oh = *((const __half2*)(g_obuf + ((size_t)row << 6)) + lane);
    float2 o  = __half22float2(oh);
    float2 mn = *((const float2*)g_mean + lane);
    float2 iv = *((const float2*)g_inv + lane);
    float2 gm = *((const float2*)gamma + lane);
    float2 bt = *((const float2*)beta + lane);
    float2 fw = *((const float2*)fcw + lane);
    float v0 = fmaxf((o.x - mn.x) * iv.x * gm.x + bt.x, 0.f) * fw.x;
    float v1 = fmaxf((o.y - mn.y) * iv.y * gm.y + bt.y, 0.f) * fw.y;
    float acc = v0 + v1;
    #pragma unroll
    for (int off = 16; off; off >>= 1)
        acc += __shfl_down_sync(0xffffffffu, acc, off);
    if (lane == 0) out[row] = acc + fcb[0];
}

// ---------------------------------------------------------------------------
extern "C" void kernel_launch(void* const* d_in, const int* in_sizes, int n_in,
                              void* d_out, int out_size) {
    const float* x     = (const float*)d_in[0];
    const float* emb   = (const float*)d_in[1];
    const float* W     = (const float*)d_in[2];
    const float* Wb    = (const float*)d_in[3];
    const float* a_src = (const float*)d_in[4];
    const float* a_dst = (const float*)d_in[5];
    const float* gamma = (const float*)d_in[6];
    const float* beta  = (const float*)d_in[7];
    const float* fcw   = (const float*)d_in[8];
    const float* fcb   = (const float*)d_in[9];
    float* out = (float*)d_out;

    pre_kernel<<<NN/8, 256>>>(emb, W, Wb, a_src, a_dst);
    cos_kernel<<<dim3(NN/64, NN/64), dim3(16, 16)>>>(emb);
    topk_kernel<<<NN, 256>>>();
    h2_kernel<<<ROWS/128, 256>>>(x, W, Wb);
    agg_kernel<<<ROWS/8, 256>>>(emb);
    red_kernel<<<RED_BLOCKS, 256>>>();
    stats_kernel<<<1, 64>>>();
    out_kernel<<<ROWS/8, 256>>>(gamma, beta, fcw, fcb, out);
}

// round 16
// speedup vs baseline: 1.1490x; 1.0424x over previous
#include <cuda_runtime.h>
#include <cuda_fp16.h>
#include <math.h>

#define NN   2048
#define TT   5
#define DD   64
#define KK   21
#define BB   32
#define ROWS (BB*NN)
#define RED_BLOCKS 128

// ---- scratch (device globals; no runtime allocation) ----
__device__ float  g_cos[NN*NN];      // 16 MB
__device__ float  g_norm[NN];
__device__ float  g_ces[NN];         // emb . a_src[64:]
__device__ float  g_ced[NN];         // emb . a_dst[64:]
__device__ float  g_ws[TT];          // W^T a_src[:64]
__device__ float  g_wd[TT];
__device__ float  g_bs[2];           // Wb.a_src[:64], Wb.a_dst[:64]
__device__ int    g_idx[NN*KK];
__device__ __half g_h[ROWS*DD];      // 8 MB (fp16; only consumer is agg gather)
__device__ float  g_esrc[ROWS];
__device__ float  g_edst[ROWS];
__device__ __half g_obuf[ROWS*DD];   // 8 MB (fp16)
__device__ float  g_part[RED_BLOCKS*128];
__device__ float  g_mean[DD];
__device__ float  g_inv[DD];

// monotonic float->uint key (total order matches float >)
__device__ __forceinline__ unsigned fkey(float f) {
    unsigned b = __float_as_uint(f);
    return (b & 0x80000000u) ? ~b : (b | 0x80000000u);
}

// ---------------------------------------------------------------------------
// 1) pre: per-node norms + emb-attention constants; warp 0 of block 0 also
//    computes the 5-dim projected attention weights.
__global__ __launch_bounds__(256) void pre_kernel(
    const float* __restrict__ emb, const float* __restrict__ W,
    const float* __restrict__ Wb,
    const float* __restrict__ a_src, const float* __restrict__ a_dst) {
    int t = threadIdx.x, lane = t & 31, w = t >> 5;
    int n = blockIdx.x * 8 + w;

    float e0 = emb[n * DD + lane], e1 = emb[n * DD + lane + 32];
    float s  = e0 * e0 + e1 * e1;
    float ps = e0 * a_src[DD + lane] + e1 * a_src[DD + lane + 32];
    float pd = e0 * a_dst[DD + lane] + e1 * a_dst[DD + lane + 32];
    #pragma unroll
    for (int off = 16; off; off >>= 1) {
        s  += __shfl_down_sync(0xffffffffu, s, off);
        ps += __shfl_down_sync(0xffffffffu, ps, off);
        pd += __shfl_down_sync(0xffffffffu, pd, off);
    }
    if (lane == 0) {
        g_norm[n] = sqrtf(s);
        g_ces[n] = ps;
        g_ced[n] = pd;
    }

    if (blockIdx.x == 0 && w == 0) {
        float a0 = a_src[lane], a1 = a_src[lane + 32];
        float d0 = a_dst[lane], d1 = a_dst[lane + 32];
        #pragma unroll
        for (int tt = 0; tt < TT; tt++) {
            float w0 = W[lane * TT + tt], w1 = W[(lane + 32) * TT + tt];
            float vs = w0 * a0 + w1 * a1;
            float vd = w0 * d0 + w1 * d1;
            #pragma unroll
            for (int off = 16; off; off >>= 1) {
                vs += __shfl_down_sync(0xffffffffu, vs, off);
                vd += __shfl_down_sync(0xffffffffu, vd, off);
            }
            if (lane == 0) { g_ws[tt] = vs; g_wd[tt] = vd; }
        }
        float b0 = Wb[lane], b1 = Wb[lane + 32];
        float vbs = b0 * a0 + b1 * a1;
        float vbd = b0 * d0 + b1 * d1;
        #pragma unroll
        for (int off = 16; off; off >>= 1) {
            vbs += __shfl_down_sync(0xffffffffu, vbs, off);
            vbd += __shfl_down_sync(0xffffffffu, vbd, off);
        }
        if (lane == 0) { g_bs[0] = vbs; g_bs[1] = vbd; }
    }
}

// ---------------------------------------------------------------------------
// 2) cos = (emb @ emb^T) / (norm_i * norm_j)   64x64 tile, 4x4 per thread
__global__ __launch_bounds__(256) void cos_kernel(const float* __restrict__ emb) {
    __shared__ float As[DD][64];
    __shared__ float Bs[DD][64];
    int bi = blockIdx.y * 64;
    int bj = blockIdx.x * 64;
    int tx = threadIdx.x, ty = threadIdx.y;
    int t  = ty * 16 + tx;

    #pragma unroll
    for (int u = 0; u < 4; u++) {
        int idx = t + u * 256;
        int row = idx >> 4;
        int c4  = idx & 15;
        float4 a = *(const float4*)(emb + (bi + row) * DD + c4 * 4);
        As[c4*4+0][row] = a.x; As[c4*4+1][row] = a.y;
        As[c4*4+2][row] = a.z; As[c4*4+3][row] = a.w;
        float4 b = *(const float4*)(emb + (bj + row) * DD + c4 * 4);
        Bs[c4*4+0][row] = b.x; Bs[c4*4+1][row] = b.y;
        Bs[c4*4+2][row] = b.z; Bs[c4*4+3][row] = b.w;
    }
    __syncthreads();

    float acc[4][4];
    #pragma unroll
    for (int u = 0; u < 4; u++)
        #pragma unroll
        for (int v = 0; v < 4; v++) acc[u][v] = 0.f;

    #pragma unroll
    for (int k = 0; k < DD; k++) {
        float4 a = *(const float4*)&As[k][ty * 4];
        float4 b = *(const float4*)&Bs[k][tx * 4];
        float ar[4] = {a.x, a.y, a.z, a.w};
        float br[4] = {b.x, b.y, b.z, b.w};
        #pragma unroll
        for (int u = 0; u < 4; u++)
            #pragma unroll
            for (int v = 0; v < 4; v++) acc[u][v] += ar[u] * br[v];
    }

    float ni[4], nj[4];
    #pragma unroll
    for (int u = 0; u < 4; u++) ni[u] = g_norm[bi + ty*4 + u];
    #pragma unroll
    for (int v = 0; v < 4; v++) nj[v] = g_norm[bj + tx*4 + v];

    #pragma unroll
    for (int u = 0; u < 4; u++) {
        int i = bi + ty*4 + u;
        #pragma unroll
        for (int v = 0; v < 4; v++) {
            int j = bj + tx*4 + v;
            g_cos[(size_t)i * NN + j] = acc[u][v] / (ni[u] * nj[v]);
        }
    }
}

// ---------------------------------------------------------------------------
// 3) top-21: per-lane sort-8 (Batcher, (key desc, idx asc)) into smem, then
//    21 pops via head pointers + redux. Warp0 merges 8 sorted 21-lists.
__global__ __launch_bounds__(256) void topk_kernel() {
    __shared__ unsigned sk[2048];
    __shared__ unsigned si[2048];
    __shared__ unsigned sck[8 * KK];
    __shared__ unsigned sci[8 * KK];
    int i = blockIdx.x;
    int t = threadIdx.x, lane = t & 31, w = t >> 5;
    int base = w * 256 + lane * 8;

    const float4* row4 = (const float4*)(g_cos + (size_t)i * NN);
    float4 aa = row4[base >> 2];
    float4 bb = row4[(base >> 2) + 1];
    float v[8] = {aa.x, aa.y, aa.z, aa.w, bb.x, bb.y, bb.z, bb.w};
    unsigned kk[8], ii[8];
    #pragma unroll
    for (int q = 0; q < 8; q++) { kk[q] = fkey(v[q]); ii[q] = base + q; }

#define CAS(a,b) { bool sw = (kk[a] < kk[b]) || (kk[a] == kk[b] && ii[a] > ii[b]); \
    unsigned k1 = sw ? kk[b] : kk[a], k2 = sw ? kk[a] : kk[b]; kk[a] = k1; kk[b] = k2; \
    unsigned i1 = sw ? ii[b] : ii[a], i2 = sw ? ii[a] : ii[b]; ii[a] = i1; ii[b] = i2; }
    CAS(0,1) CAS(2,3) CAS(4,5) CAS(6,7)
    CAS(0,2) CAS(1,3) CAS(4,6) CAS(5,7)
    CAS(1,2) CAS(5,6)
    CAS(0,4) CAS(1,5) CAS(2,6) CAS(3,7)
    CAS(2,4) CAS(3,5)
    CAS(1,2) CAS(3,4) CAS(5,6)
#undef CAS

    int sb = t * 8;
    #pragma unroll
    for (int q = 0; q < 8; q++) { sk[sb + q] = kk[q]; si[sb + q] = ii[q]; }

    int hp = 0;
    #pragma unroll 1
    for (int k = 0; k < KK; k++) {
        int hc = (hp < 8) ? hp : 7;
        unsigned kcur = sk[sb + hc];
        unsigned icur = si[sb + hc];
        if (hp >= 8) kcur = 0u;
        unsigned mk = __reduce_max_sync(0xffffffffu, kcur);
        unsigned cand = (kcur == mk) ? icur : 0xffffffffu;
        unsigned wi = __reduce_min_sync(0xffffffffu, cand);
        if (lane == 0) { sck[w * KK + k] = mk; sci[w * KK + k] = wi; }
        hp += (kcur == mk && icur == wi) ? 1 : 0;
    }
    __syncthreads();

    if (w == 0) {
        bool act = lane < 8;
        int hp2 = 0;
        #pragma unroll 1
        for (int k = 0; k < KK; k++) {
            int hc = (hp2 < KK) ? hp2 : KK - 1;
            unsigned kcur = act ? sck[lane * KK + hc] : 0u;
            unsigned icur = act ? sci[lane * KK + hc] : 0xffffffffu;
            if (hp2 >= KK) kcur = 0u;
            unsigned mk = __reduce_max_sync(0xffffffffu, kcur);
            unsigned cand = (kcur == mk) ? icur : 0xffffffffu;
            unsigned wi = __reduce_min_sync(0xffffffffu, cand);
            if (lane == 0) g_idx[i * KK + k] = (int)wi;
            hp2 += (kcur == mk && icur == wi) ? 1 : 0;
        }
    }
}

// ---------------------------------------------------------------------------
// 4) h = x @ W^T + Wb -> fp16; e_src/e_dst via 5-dim dots (fp32 exact).
__global__ __launch_bounds__(256) void h2_kernel(
    const float* __restrict__ x, const float* __restrict__ W,
    const float* __restrict__ Wb) {
    __shared__ float sx[128 * TT];
    __shared__ float sW[DD * TT];
    __shared__ float sWb[DD];
    int t = threadIdx.x;
    for (int q = t; q < 128 * TT; q += 256) sx[q] = x[blockIdx.x * 128 * TT + q];
    for (int q = t; q < DD * TT; q += 256) sW[q] = W[q];
    if (t < DD) sWb[t] = Wb[t];
    __syncthreads();

    int cq = t & 15;
    int r0 = t >> 4;

    float wr[20], b4[4];
    #pragma unroll
    for (int j = 0; j < 4; j++) {
        #pragma unroll
        for (int tt = 0; tt < TT; tt++) wr[j * TT + tt] = sW[(cq * 4 + j) * TT + tt];
        b4[j] = sWb[cq * 4 + j];
    }
    float ws[TT], wd[TT];
    #pragma unroll
    for (int tt = 0; tt < TT; tt++) { ws[tt] = g_ws[tt]; wd[tt] = g_wd[tt]; }
    float bs0 = g_bs[0], bd0 = g_bs[1];

    #pragma unroll 1
    for (int g = 0; g < 8; g++) {
        int rl = g * 16 + r0;
        int row = blockIdx.x * 128 + rl;
        float xv[TT];
        #pragma unroll
        for (int tt = 0; tt < TT; tt++) xv[tt] = sx[rl * TT + tt];

        float h[4];
        #pragma unroll
        for (int j = 0; j < 4; j++) {
            float acc = b4[j];
            #pragma unroll
            for (int tt = 0; tt < TT; tt++) acc += xv[tt] * wr[j * TT + tt];
            h[j] = acc;
        }
        __half2 p0 = __floats2half2_rn(h[0], h[1]);
        __half2 p1 = __floats2half2_rn(h[2], h[3]);
        uint2 pk = make_uint2(*(unsigned*)&p0, *(unsigned*)&p1);
        *(uint2*)(g_h + ((size_t)row << 6) + cq * 4) = pk;

        if (cq == 0) {
            float es = bs0, ed = bd0;
            #pragma unroll
            for (int tt = 0; tt < TT; tt++) {
                es += xv[tt] * ws[tt];
                ed += xv[tt] * wd[tt];
            }
            int n = row & (NN - 1);
            g_esrc[row] = es + g_ces[n];
            g_edst[row] = ed + g_ced[n];
        }
    }
}

// ---------------------------------------------------------------------------
// 5) sparse attention + z*emb. Warp per row. Gather: quarter-warp per
//    neighbor — lane quad q serves neighbor 4p+q, lane loads uint4 = 8
//    fp16 channels; 6 iterations cover 21 neighbors (pads have weight 0).
//    Final xor-8/xor-16 combine; lanes 0-7 store the 128 B fp16 row.
__global__ __launch_bounds__(256) void agg_kernel(const float* __restrict__ emb) {
    int t = threadIdx.x, w = t >> 5, lane = t & 31;
    int row = blockIdx.x * 8 + w;
    int b = row >> 11;
    int i = row & (NN - 1);

    float es = g_esrc[row];
    float e = -3e38f; int j = 0;
    if (lane < KK) {
        j = g_idx[i * KK + lane];
        float v = es + g_edst[(b << 11) + j];
        e = (v > 0.f) ? v : 0.2f * v;
    }
    float m = e;
    #pragma unroll
    for (int off = 16; off; off >>= 1)
        m = fmaxf(m, __shfl_xor_sync(0xffffffffu, m, off));
    float wgt = (lane < KK) ? __expf(e - m) : 0.f;
    float s = wgt;
    #pragma unroll
    for (int off = 16; off; off >>= 1)
        s += __shfl_xor_sync(0xffffffffu, s, off);

    int q  = lane >> 3;          // quad 0..3
    int cg = lane & 7;           // channel group: channels 8cg..8cg+7
    float acc[8];
    #pragma unroll
    for (int c = 0; c < 8; c++) acc[c] = 0.f;

    #pragma unroll
    for (int p = 0; p < 6; p++) {
        int nsel = 4 * p + q;                                // 0..23
        float wk = __shfl_sync(0xffffffffu, wgt, nsel);      // lanes 21-31: wgt 0
        int   jk = __shfl_sync(0xffffffffu, j, nsel);        // lanes>=21: j=0, safe
        const uint4* hp = (const uint4*)(g_h + ((size_t)((b << 11) + jk) << 6));
        uint4 hv = hp[cg];
        float2 f0 = __half22float2(*(__half2*)&hv.x);
        float2 f1 = __half22float2(*(__half2*)&hv.y);
        float2 f2 = __half22float2(*(__half2*)&hv.z);
        float2 f3 = __half22float2(*(__half2*)&hv.w);
        acc[0] += wk * f0.x; acc[1] += wk * f0.y;
        acc[2] += wk * f1.x; acc[3] += wk * f1.y;
        acc[4] += wk * f2.x; acc[5] += wk * f2.y;
        acc[6] += wk * f3.x; acc[7] += wk * f3.y;
    }

    // combine quads (cg invariant under xor 8/16)
    #pragma unroll
    for (int c = 0; c < 8; c++) acc[c] += __shfl_xor_sync(0xffffffffu, acc[c], 8);
    #pragma unroll
    for (int c = 0; c < 8; c++) acc[c] += __shfl_xor_sync(0xffffffffu, acc[c], 16);

    if (q == 0) {
        float rs = 1.f / s;
        float4 e0 = *((const float4*)(emb + i * DD) + cg * 2);
        float4 e1 = *((const float4*)(emb + i * DD) + cg * 2 + 1);
        float o0 = fmaxf(acc[0] * rs, 0.f) * e0.x;
        float o1 = fmaxf(acc[1] * rs, 0.f) * e0.y;
        float o2 = fmaxf(acc[2] * rs, 0.f) * e0.z;
        float o3 = fmaxf(acc[3] * rs, 0.f) * e0.w;
        float o4 = fmaxf(acc[4] * rs, 0.f) * e1.x;
        float o5 = fmaxf(acc[5] * rs, 0.f) * e1.y;
        float o6 = fmaxf(acc[6] * rs, 0.f) * e1.z;
        float o7 = fmaxf(acc[7] * rs, 0.f) * e1.w;
        __half2 h0 = __floats2half2_rn(o0, o1);
        __half2 h1 = __floats2half2_rn(o2, o3);
        __half2 h2 = __floats2half2_rn(o4, o5);
        __half2 h3 = __floats2half2_rn(o6, o7);
        uint4 pk;
        pk.x = *(unsigned*)&h0; pk.y = *(unsigned*)&h1;
        pk.z = *(unsigned*)&h2; pk.w = *(unsigned*)&h3;
        *((uint4*)(g_obuf + ((size_t)row << 6)) + cg) = pk;
    }
}

// ---------------------------------------------------------------------------
// 6) BN stats partial reduce over fp16 obuf (uint4 = 8 halves per thread;
//    thread t owns channels 8*(t&7)..+7; deterministic regroup, addr ≡ t+64k)
__global__ __launch_bounds__(256) void red_kernel() {
    __shared__ float ss[256 * 8], sq[256 * 8];
    int t = threadIdx.x;
    int gt = blockIdx.x * 256 + t;
    const uint4* p = (const uint4*)g_obuf;
    float s[8], q[8];
    #pragma unroll
    for (int jj = 0; jj < 8; jj++) { s[jj] = 0.f; q[jj] = 0.f; }
    const int total = ROWS * DD / 8;           // 524288 uint4
    for (int idx = gt; idx < total; idx += RED_BLOCKS * 256) {
        uint4 v = p[idx];
        float2 f0 = __half22float2(*(__half2*)&v.x);
        float2 f1 = __half22float2(*(__half2*)&v.y);
        float2 f2 = __half22float2(*(__half2*)&v.z);
        float2 f3 = __half22float2(*(__half2*)&v.w);
        s[0] += f0.x; q[0] += f0.x * f0.x;
        s[1] += f0.y; q[1] += f0.y * f0.y;
        s[2] += f1.x; q[2] += f1.x * f1.x;
        s[3] += f1.y; q[3] += f1.y * f1.y;
        s[4] += f2.x; q[4] += f2.x * f2.x;
        s[5] += f2.y; q[5] += f2.y * f2.y;
        s[6] += f3.x; q[6] += f3.x * f3.x;
        s[7] += f3.y; q[7] += f3.y * f3.y;
    }
    #pragma unroll
    for (int jj = 0; jj < 8; jj++) { ss[t * 8 + jj] = s[jj]; sq[t * 8 + jj] = q[jj]; }
    __syncthreads();
    if (t < DD) {
        float a = 0.f, b2 = 0.f;
        #pragma unroll 8
        for (int k = 0; k < 32; k++) {
            int thr = (t >> 3) + 8 * k;
            a  += ss[thr * 8 + (t & 7)];
            b2 += sq[thr * 8 + (t & 7)];
        }
        g_part[blockIdx.x * 128 + t]      = a;
        g_part[blockIdx.x * 128 + 64 + t] = b2;
    }
}

// 7) finalize mean / rsqrt(var+eps)
__global__ void stats_kernel() {
    int c = threadIdx.x;  // 64
    float s = 0.f, s2 = 0.f;
    for (int bk = 0; bk < RED_BLOCKS; bk++) {
        s  += g_part[bk * 128 + c];
        s2 += g_part[bk * 128 + 64 + c];
    }
    float mean = s / (float)ROWS;
    float var  = s2 / (float)ROWS - mean * mean;
    g_mean[c] = mean;
    g_inv[c]  = rsqrtf(var + 1e-5f);
}

// ---------------------------------------------------------------------------
// 8) BN apply + relu + fc  (warp per row, half2 in, channels 2l/2l+1)
__global__ __launch_bounds__(256) void out_kernel(
    const float* __restrict__ gamma, const float* __restrict__ beta,
    const float* __restrict__ fcw, const float* __restrict__ fcb,
    float* __restrict__ out) {
    int t = threadIdx.x, w = t >> 5, lane = t & 31;
    int row = blockIdx.x * 8 + w;
    __half2 oh = *((const __half2*)(g_obuf + ((size_t)row << 6)) + lane);
    float2 o  = __half22float2(oh);
    float2 mn = *((const float2*)g_mean + lane);
    float2 iv = *((const float2*)g_inv + lane);
    float2 gm = *((const float2*)gamma + lane);
    float2 bt = *((const float2*)beta + lane);
    float2 fw = *((const float2*)fcw + lane);
    float v0 = fmaxf((o.x - mn.x) * iv.x * gm.x + bt.x, 0.f) * fw.x;
    float v1 = fmaxf((o.y - mn.y) * iv.y * gm.y + bt.y, 0.f) * fw.y;
    float acc = v0 + v1;
    #pragma unroll
    for (int off = 16; off; off >>= 1)
        acc += __shfl_down_sync(0xffffffffu, acc, off);
    if (lane == 0) out[row] = acc + fcb[0];
}

// ---------------------------------------------------------------------------
extern "C" void kernel_launch(void* const* d_in, const int* in_sizes, int n_in,
                              void* d_out, int out_size) {
    const float* x     = (const float*)d_in[0];
    const float* emb   = (const float*)d_in[1];
    const float* W     = (const float*)d_in[2];
    const float* Wb    = (const float*)d_in[3];
    const float* a_src = (const float*)d_in[4];
    const float* a_dst = (const float*)d_in[5];
    const float* gamma = (const float*)d_in[6];
    const float* beta  = (const float*)d_in[7];
    const float* fcw   = (const float*)d_in[8];
    const float* fcb   = (const float*)d_in[9];
    float* out = (float*)d_out;

    pre_kernel<<<NN/8, 256>>>(emb, W, Wb, a_src, a_dst);
    cos_kernel<<<dim3(NN/64, NN/64), dim3(16, 16)>>>(emb);
    topk_kernel<<<NN, 256>>>();
    h2_kernel<<<ROWS/128, 256>>>(x, W, Wb);
    agg_kernel<<<ROWS/8, 256>>>(emb);
    red_kernel<<<RED_BLOCKS, 256>>>();
    stats_kernel<<<1, 64>>>();
    out_kernel<<<ROWS/8, 256>>>(gamma, beta, fcw, fcb, out);
}

// round 17
// speedup vs baseline: 1.2559x; 1.0930x over previous
#include <cuda_runtime.h>
#include <cuda_fp16.h>
#include <math.h>

#define NN   2048
#define TT   5
#define DD   64
#define KK   21
#define BB   32
#define ROWS (BB*NN)
#define RED_BLOCKS 128

// ---- scratch (device globals; no runtime allocation) ----
__device__ float  g_cos[NN*NN];      // 16 MB
__device__ float  g_norm[NN];
__device__ float  g_ces[NN];         // emb . a_src[64:]
__device__ float  g_ced[NN];         // emb . a_dst[64:]
__device__ float  g_ws[TT];          // W^T a_src[:64]
__device__ float  g_wd[TT];
__device__ float  g_bs[2];           // Wb.a_src[:64], Wb.a_dst[:64]
__device__ int    g_idx[NN*KK];
__device__ __half g_h[ROWS*DD];      // 8 MB (fp16; only consumer is agg gather)
__device__ float  g_esrc[ROWS];
__device__ float  g_edst[ROWS];
__device__ __half g_obuf[ROWS*DD];   // 8 MB (fp16)
__device__ float  g_part[RED_BLOCKS*128];
__device__ float  g_mean[DD];
__device__ float  g_inv[DD];

// monotonic float->uint key (total order matches float >)
__device__ __forceinline__ unsigned fkey(float f) {
    unsigned b = __float_as_uint(f);
    return (b & 0x80000000u) ? ~b : (b | 0x80000000u);
}

// ---------------------------------------------------------------------------
// 1) pre: per-node norms + emb-attention constants; warp 0 of block 0 also
//    computes the 5-dim projected attention weights.
__global__ __launch_bounds__(256) void pre_kernel(
    const float* __restrict__ emb, const float* __restrict__ W,
    const float* __restrict__ Wb,
    const float* __restrict__ a_src, const float* __restrict__ a_dst) {
    int t = threadIdx.x, lane = t & 31, w = t >> 5;
    int n = blockIdx.x * 8 + w;

    float e0 = emb[n * DD + lane], e1 = emb[n * DD + lane + 32];
    float s  = e0 * e0 + e1 * e1;
    float ps = e0 * a_src[DD + lane] + e1 * a_src[DD + lane + 32];
    float pd = e0 * a_dst[DD + lane] + e1 * a_dst[DD + lane + 32];
    #pragma unroll
    for (int off = 16; off; off >>= 1) {
        s  += __shfl_down_sync(0xffffffffu, s, off);
        ps += __shfl_down_sync(0xffffffffu, ps, off);
        pd += __shfl_down_sync(0xffffffffu, pd, off);
    }
    if (lane == 0) {
        g_norm[n] = sqrtf(s);
        g_ces[n] = ps;
        g_ced[n] = pd;
    }

    if (blockIdx.x == 0 && w == 0) {
        float a0 = a_src[lane], a1 = a_src[lane + 32];
        float d0 = a_dst[lane], d1 = a_dst[lane + 32];
        #pragma unroll
        for (int tt = 0; tt < TT; tt++) {
            float w0 = W[lane * TT + tt], w1 = W[(lane + 32) * TT + tt];
            float vs = w0 * a0 + w1 * a1;
            float vd = w0 * d0 + w1 * d1;
            #pragma unroll
            for (int off = 16; off; off >>= 1) {
                vs += __shfl_down_sync(0xffffffffu, vs, off);
                vd += __shfl_down_sync(0xffffffffu, vd, off);
            }
            if (lane == 0) { g_ws[tt] = vs; g_wd[tt] = vd; }
        }
        float b0 = Wb[lane], b1 = Wb[lane + 32];
        float vbs = b0 * a0 + b1 * a1;
        float vbd = b0 * d0 + b1 * d1;
        #pragma unroll
        for (int off = 16; off; off >>= 1) {
            vbs += __shfl_down_sync(0xffffffffu, vbs, off);
            vbd += __shfl_down_sync(0xffffffffu, vbd, off);
        }
        if (lane == 0) { g_bs[0] = vbs; g_bs[1] = vbd; }
    }
}

// ---------------------------------------------------------------------------
// 2) cos = (emb @ emb^T) / (norm_i * norm_j) — SYMMETRIC: only tiles with
//    bj >= bi computed; off-diagonal tiles mirror via smem transpose.
//    Values bit-identical to the full computation (same k-order both sides).
__global__ __launch_bounds__(256) void cos_kernel(const float* __restrict__ emb) {
    __shared__ float As[DD][64];
    __shared__ float Bs[DD][64];
    __shared__ float T[64 * 65];
    if (blockIdx.x < blockIdx.y) return;   // upper triangle only (bj >= bi)
    int bi = blockIdx.y * 64;
    int bj = blockIdx.x * 64;
    int tx = threadIdx.x, ty = threadIdx.y;
    int t  = ty * 16 + tx;

    #pragma unroll
    for (int u = 0; u < 4; u++) {
        int idx = t + u * 256;
        int row = idx >> 4;
        int c4  = idx & 15;
        float4 a = *(const float4*)(emb + (bi + row) * DD + c4 * 4);
        As[c4*4+0][row] = a.x; As[c4*4+1][row] = a.y;
        As[c4*4+2][row] = a.z; As[c4*4+3][row] = a.w;
        float4 b = *(const float4*)(emb + (bj + row) * DD + c4 * 4);
        Bs[c4*4+0][row] = b.x; Bs[c4*4+1][row] = b.y;
        Bs[c4*4+2][row] = b.z; Bs[c4*4+3][row] = b.w;
    }
    __syncthreads();

    float acc[4][4];
    #pragma unroll
    for (int u = 0; u < 4; u++)
        #pragma unroll
        for (int v = 0; v < 4; v++) acc[u][v] = 0.f;

    #pragma unroll
    for (int k = 0; k < DD; k++) {
        float4 a = *(const float4*)&As[k][ty * 4];
        float4 b = *(const float4*)&Bs[k][tx * 4];
        float ar[4] = {a.x, a.y, a.z, a.w};
        float br[4] = {b.x, b.y, b.z, b.w};
        #pragma unroll
        for (int u = 0; u < 4; u++)
            #pragma unroll
            for (int v = 0; v < 4; v++) acc[u][v] += ar[u] * br[v];
    }

    float ni[4], nj[4];
    #pragma unroll
    for (int u = 0; u < 4; u++) ni[u] = g_norm[bi + ty*4 + u];
    #pragma unroll
    for (int v = 0; v < 4; v++) nj[v] = g_norm[bj + tx*4 + v];

    float o[4][4];
    #pragma unroll
    for (int u = 0; u < 4; u++) {
        int i = bi + ty*4 + u;
        #pragma unroll
        for (int v = 0; v < 4; v++) {
            int j = bj + tx*4 + v;
            o[u][v] = acc[u][v] / (ni[u] * nj[v]);
            g_cos[(size_t)i * NN + j] = o[u][v];
        }
    }

    if (bi != bj) {
        // mirror: stage transposed tile in smem, write coalesced
        #pragma unroll
        for (int u = 0; u < 4; u++)
            #pragma unroll
            for (int v = 0; v < 4; v++)
                T[(tx*4 + v) * 65 + (ty*4 + u)] = o[u][v];
        __syncthreads();
        int r  = t >> 2;          // 0..63  (row of transposed tile = col j-local)
        int c4 = t & 3;           // 4 float4 groups of 16 cols each
        #pragma unroll
        for (int g = 0; g < 4; g++) {
            int c = c4 * 16 + g * 4;
            float4 vv;
            vv.x = T[r * 65 + c + 0];
            vv.y = T[r * 65 + c + 1];
            vv.z = T[r * 65 + c + 2];
            vv.w = T[r * 65 + c + 3];
            *(float4*)(g_cos + (size_t)(bj + r) * NN + bi + c) = vv;
        }
    }
}

// ---------------------------------------------------------------------------
// 3) top-21: per-lane sort-8 (Batcher, (key desc, idx asc)) into smem, then
//    21 pops via head pointers + redux. Warp0 merges 8 sorted 21-lists.
__global__ __launch_bounds__(256) void topk_kernel() {
    __shared__ unsigned sk[2048];
    __shared__ unsigned si[2048];
    __shared__ unsigned sck[8 * KK];
    __shared__ unsigned sci[8 * KK];
    int i = blockIdx.x;
    int t = threadIdx.x, lane = t & 31, w = t >> 5;
    int base = w * 256 + lane * 8;

    const float4* row4 = (const float4*)(g_cos + (size_t)i * NN);
    float4 aa = row4[base >> 2];
    float4 bb = row4[(base >> 2) + 1];
    float v[8] = {aa.x, aa.y, aa.z, aa.w, bb.x, bb.y, bb.z, bb.w};
    unsigned kk[8], ii[8];
    #pragma unroll
    for (int q = 0; q < 8; q++) { kk[q] = fkey(v[q]); ii[q] = base + q; }

#define CAS(a,b) { bool sw = (kk[a] < kk[b]) || (kk[a] == kk[b] && ii[a] > ii[b]); \
    unsigned k1 = sw ? kk[b] : kk[a], k2 = sw ? kk[a] : kk[b]; kk[a] = k1; kk[b] = k2; \
    unsigned i1 = sw ? ii[b] : ii[a], i2 = sw ? ii[a] : ii[b]; ii[a] = i1; ii[b] = i2; }
    CAS(0,1) CAS(2,3) CAS(4,5) CAS(6,7)
    CAS(0,2) CAS(1,3) CAS(4,6) CAS(5,7)
    CAS(1,2) CAS(5,6)
    CAS(0,4) CAS(1,5) CAS(2,6) CAS(3,7)
    CAS(2,4) CAS(3,5)
    CAS(1,2) CAS(3,4) CAS(5,6)
#undef CAS

    int sb = t * 8;
    #pragma unroll
    for (int q = 0; q < 8; q++) { sk[sb + q] = kk[q]; si[sb + q] = ii[q]; }

    int hp = 0;
    #pragma unroll 1
    for (int k = 0; k < KK; k++) {
        int hc = (hp < 8) ? hp : 7;
        unsigned kcur = sk[sb + hc];
        unsigned icur = si[sb + hc];
        if (hp >= 8) kcur = 0u;
        unsigned mk = __reduce_max_sync(0xffffffffu, kcur);
        unsigned cand = (kcur == mk) ? icur : 0xffffffffu;
        unsigned wi = __reduce_min_sync(0xffffffffu, cand);
        if (lane == 0) { sck[w * KK + k] = mk; sci[w * KK + k] = wi; }
        hp += (kcur == mk && icur == wi) ? 1 : 0;
    }
    __syncthreads();

    if (w == 0) {
        bool act = lane < 8;
        int hp2 = 0;
        #pragma unroll 1
        for (int k = 0; k < KK; k++) {
            int hc = (hp2 < KK) ? hp2 : KK - 1;
            unsigned kcur = act ? sck[lane * KK + hc] : 0u;
            unsigned icur = act ? sci[lane * KK + hc] : 0xffffffffu;
            if (hp2 >= KK) kcur = 0u;
            unsigned mk = __reduce_max_sync(0xffffffffu, kcur);
            unsigned cand = (kcur == mk) ? icur : 0xffffffffu;
            unsigned wi = __reduce_min_sync(0xffffffffu, cand);
            if (lane == 0) g_idx[i * KK + k] = (int)wi;
            hp2 += (kcur == mk && icur == wi) ? 1 : 0;
        }
    }
}

// ---------------------------------------------------------------------------
// 4) h = x @ W^T + Wb -> fp16; e_src/e_dst via 5-dim dots (fp32 exact).
__global__ __launch_bounds__(256) void h2_kernel(
    const float* __restrict__ x, const float* __restrict__ W,
    const float* __restrict__ Wb) {
    __shared__ float sx[128 * TT];
    __shared__ float sW[DD * TT];
    __shared__ float sWb[DD];
    int t = threadIdx.x;
    for (int q = t; q < 128 * TT; q += 256) sx[q] = x[blockIdx.x * 128 * TT + q];
    for (int q = t; q < DD * TT; q += 256) sW[q] = W[q];
    if (t < DD) sWb[t] = Wb[t];
    __syncthreads();

    int cq = t & 15;
    int r0 = t >> 4;

    float wr[20], b4[4];
    #pragma unroll
    for (int j = 0; j < 4; j++) {
        #pragma unroll
        for (int tt = 0; tt < TT; tt++) wr[j * TT + tt] = sW[(cq * 4 + j) * TT + tt];
        b4[j] = sWb[cq * 4 + j];
    }
    float ws[TT], wd[TT];
    #pragma unroll
    for (int tt = 0; tt < TT; tt++) { ws[tt] = g_ws[tt]; wd[tt] = g_wd[tt]; }
    float bs0 = g_bs[0], bd0 = g_bs[1];

    #pragma unroll 1
    for (int g = 0; g < 8; g++) {
        int rl = g * 16 + r0;
        int row = blockIdx.x * 128 + rl;
        float xv[TT];
        #pragma unroll
        for (int tt = 0; tt < TT; tt++) xv[tt] = sx[rl * TT + tt];

        float h[4];
        #pragma unroll
        for (int j = 0; j < 4; j++) {
            float acc = b4[j];
            #pragma unroll
            for (int tt = 0; tt < TT; tt++) acc += xv[tt] * wr[j * TT + tt];
            h[j] = acc;
        }
        __half2 p0 = __floats2half2_rn(h[0], h[1]);
        __half2 p1 = __floats2half2_rn(h[2], h[3]);
        uint2 pk = make_uint2(*(unsigned*)&p0, *(unsigned*)&p1);
        *(uint2*)(g_h + ((size_t)row << 6) + cq * 4) = pk;

        if (cq == 0) {
            float es = bs0, ed = bd0;
            #pragma unroll
            for (int tt = 0; tt < TT; tt++) {
                es += xv[tt] * ws[tt];
                ed += xv[tt] * wd[tt];
            }
            int n = row & (NN - 1);
            g_esrc[row] = es + g_ces[n];
            g_edst[row] = ed + g_ced[n];
        }
    }
}

// ---------------------------------------------------------------------------
// 5) sparse attention + z*emb. Warp per row. Gather: quarter-warp per
//    neighbor — lane quad q serves neighbor 4p+q, lane loads uint4 = 8
//    fp16 channels; 6 iterations cover 21 neighbors (pads have weight 0).
//    Final xor-8/xor-16 combine; lanes 0-7 store the 128 B fp16 row.
__global__ __launch_bounds__(256) void agg_kernel(const float* __restrict__ emb) {
    int t = threadIdx.x, w = t >> 5, lane = t & 31;
    int row = blockIdx.x * 8 + w;
    int b = row >> 11;
    int i = row & (NN - 1);

    float es = g_esrc[row];
    float e = -3e38f; int j = 0;
    if (lane < KK) {
        j = g_idx[i * KK + lane];
        float v = es + g_edst[(b << 11) + j];
        e = (v > 0.f) ? v : 0.2f * v;
    }
    float m = e;
    #pragma unroll
    for (int off = 16; off; off >>= 1)
        m = fmaxf(m, __shfl_xor_sync(0xffffffffu, m, off));
    float wgt = (lane < KK) ? __expf(e - m) : 0.f;
    float s = wgt;
    #pragma unroll
    for (int off = 16; off; off >>= 1)
        s += __shfl_xor_sync(0xffffffffu, s, off);

    int q  = lane >> 3;          // quad 0..3
    int cg = lane & 7;           // channel group: channels 8cg..8cg+7
    float acc[8];
    #pragma unroll
    for (int c = 0; c < 8; c++) acc[c] = 0.f;

    #pragma unroll
    for (int p = 0; p < 6; p++) {
        int nsel = 4 * p + q;                                // 0..23
        float wk = __shfl_sync(0xffffffffu, wgt, nsel);      // lanes 21-31: wgt 0
        int   jk = __shfl_sync(0xffffffffu, j, nsel);        // lanes>=21: j=0, safe
        const uint4* hp = (const uint4*)(g_h + ((size_t)((b << 11) + jk) << 6));
        uint4 hv = hp[cg];
        float2 f0 = __half22float2(*(__half2*)&hv.x);
        float2 f1 = __half22float2(*(__half2*)&hv.y);
        float2 f2 = __half22float2(*(__half2*)&hv.z);
        float2 f3 = __half22float2(*(__half2*)&hv.w);
        acc[0] += wk * f0.x; acc[1] += wk * f0.y;
        acc[2] += wk * f1.x; acc[3] += wk * f1.y;
        acc[4] += wk * f2.x; acc[5] += wk * f2.y;
        acc[6] += wk * f3.x; acc[7] += wk * f3.y;
    }

    // combine quads (cg invariant under xor 8/16)
    #pragma unroll
    for (int c = 0; c < 8; c++) acc[c] += __shfl_xor_sync(0xffffffffu, acc[c], 8);
    #pragma unroll
    for (int c = 0; c < 8; c++) acc[c] += __shfl_xor_sync(0xffffffffu, acc[c], 16);

    if (q == 0) {
        float rs = 1.f / s;
        float4 e0 = *((const float4*)(emb + i * DD) + cg * 2);
        float4 e1 = *((const float4*)(emb + i * DD) + cg * 2 + 1);
        float o0 = fmaxf(acc[0] * rs, 0.f) * e0.x;
        float o1 = fmaxf(acc[1] * rs, 0.f) * e0.y;
        float o2 = fmaxf(acc[2] * rs, 0.f) * e0.z;
        float o3 = fmaxf(acc[3] * rs, 0.f) * e0.w;
        float o4 = fmaxf(acc[4] * rs, 0.f) * e1.x;
        float o5 = fmaxf(acc[5] * rs, 0.f) * e1.y;
        float o6 = fmaxf(acc[6] * rs, 0.f) * e1.z;
        float o7 = fmaxf(acc[7] * rs, 0.f) * e1.w;
        __half2 h0 = __floats2half2_rn(o0, o1);
        __half2 h1 = __floats2half2_rn(o2, o3);
        __half2 h2 = __floats2half2_rn(o4, o5);
        __half2 h3 = __floats2half2_rn(o6, o7);
        uint4 pk;
        pk.x = *(unsigned*)&h0; pk.y = *(unsigned*)&h1;
        pk.z = *(unsigned*)&h2; pk.w = *(unsigned*)&h3;
        *((uint4*)(g_obuf + ((size_t)row << 6)) + cg) = pk;
    }
}

// ---------------------------------------------------------------------------
// 6) BN stats partial reduce over fp16 obuf (uint4 = 8 halves per thread;
//    thread t owns channels 8*(t&7)..+7; deterministic regroup, addr ≡ t+64k)
__global__ __launch_bounds__(256) void red_kernel() {
    __shared__ float ss[256 * 8], sq[256 * 8];
    int t = threadIdx.x;
    int gt = blockIdx.x * 256 + t;
    const uint4* p = (const uint4*)g_obuf;
    float s[8], q[8];
    #pragma unroll
    for (int jj = 0; jj < 8; jj++) { s[jj] = 0.f; q[jj] = 0.f; }
    const int total = ROWS * DD / 8;           // 524288 uint4
    for (int idx = gt; idx < total; idx += RED_BLOCKS * 256) {
        uint4 v = p[idx];
        float2 f0 = __half22float2(*(__half2*)&v.x);
        float2 f1 = __half22float2(*(__half2*)&v.y);
        float2 f2 = __half22float2(*(__half2*)&v.z);
        float2 f3 = __half22float2(*(__half2*)&v.w);
        s[0] += f0.x; q[0] += f0.x * f0.x;
        s[1] += f0.y; q[1] += f0.y * f0.y;
        s[2] += f1.x; q[2] += f1.x * f1.x;
        s[3] += f1.y; q[3] += f1.y * f1.y;
        s[4] += f2.x; q[4] += f2.x * f2.x;
        s[5] += f2.y; q[5] += f2.y * f2.y;
        s[6] += f3.x; q[6] += f3.x * f3.x;
        s[7] += f3.y; q[7] += f3.y * f3.y;
    }
    #pragma unroll
    for (int jj = 0; jj < 8; jj++) { ss[t * 8 + jj] = s[jj]; sq[t * 8 + jj] = q[jj]; }
    __syncthreads();
    if (t < DD) {
        float a = 0.f, b2 = 0.f;
        #pragma unroll 8
        for (int k = 0; k < 32; k++) {
            int thr = (t >> 3) + 8 * k;
            a  += ss[thr * 8 + (t & 7)];
            b2 += sq[thr * 8 + (t & 7)];
        }
        g_part[blockIdx.x * 128 + t]      = a;
        g_part[blockIdx.x * 128 + 64 + t] = b2;
    }
}

// 7) finalize mean / rsqrt(var+eps)
__global__ void stats_kernel() {
    int c = threadIdx.x;  // 64
    float s = 0.f, s2 = 0.f;
    for (int bk = 0; bk < RED_BLOCKS; bk++) {
        s  += g_part[bk * 128 + c];
        s2 += g_part[bk * 128 + 64 + c];
    }
    float mean = s / (float)ROWS;
    float var  = s2 / (float)ROWS - mean * mean;
    g_mean[c] = mean;
    g_inv[c]  = rsqrtf(var + 1e-5f);
}

// ---------------------------------------------------------------------------
// 8) BN apply + relu + fc  (warp per row, half2 in, channels 2l/2l+1)
__global__ __launch_bounds__(256) void out_kernel(
    const float* __restrict__ gamma, const float* __restrict__ beta,
    const float* __restrict__ fcw, const float* __restrict__ fcb,
    float* __restrict__ out) {
    int t = threadIdx.x, w = t >> 5, lane = t & 31;
    int row = blockIdx.x * 8 + w;
    __half2 oh = *((const __half2*)(g_obuf + ((size_t)row << 6)) + lane);
    float2 o  = __half22float2(oh);
    float2 mn = *((const float2*)g_mean + lane);
    float2 iv = *((const float2*)g_inv + lane);
    float2 gm = *((const float2*)gamma + lane);
    float2 bt = *((const float2*)beta + lane);
    float2 fw = *((const float2*)fcw + lane);
    float v0 = fmaxf((o.x - mn.x) * iv.x * gm.x + bt.x, 0.f) * fw.x;
    float v1 = fmaxf((o.y - mn.y) * iv.y * gm.y + bt.y, 0.f) * fw.y;
    float acc = v0 + v1;
    #pragma unroll
    for (int off = 16; off; off >>= 1)
        acc += __shfl_down_sync(0xffffffffu, acc, off);
    if (lane == 0) out[row] = acc + fcb[0];
}

// ---------------------------------------------------------------------------
extern "C" void kernel_launch(void* const* d_in, const int* in_sizes, int n_in,
                              void* d_out, int out_size) {
    const float* x     = (const float*)d_in[0];
    const float* emb   = (const float*)d_in[1];
    const float* W     = (const float*)d_in[2];
    const float* Wb    = (const float*)d_in[3];
    const float* a_src = (const float*)d_in[4];
    const float* a_dst = (const float*)d_in[5];
    const float* gamma = (const float*)d_in[6];
    const float* beta  = (const float*)d_in[7];
    const float* fcw   = (const float*)d_in[8];
    const float* fcb   = (const float*)d_in[9];
    float* out = (float*)d_out;

    pre_kernel<<<NN/8, 256>>>(emb, W, Wb, a_src, a_dst);
    cos_kernel<<<dim3(NN/64, NN/64), dim3(16, 16)>>>(emb);
    topk_kernel<<<NN, 256>>>();
    h2_kernel<<<ROWS/128, 256>>>(x, W, Wb);
    agg_kernel<<<ROWS/8, 256>>>(emb);
    red_kernel<<<RED_BLOCKS, 256>>>();
    stats_kernel<<<1, 64>>>();
    out_kernel<<<ROWS/8, 256>>>(gamma, beta, fcw, fcb, out);
}